// round 1
// baseline (speedup 1.0000x reference)
#include <cuda_runtime.h>
#include <cuda_bf16.h>
#include <cstddef>

// Problem constants
constexpr int B_   = 128;
constexpr int NI   = 100;
constexpr int NS   = 50;
constexpr int OBJ  = 2048;
constexpr int SEM  = 300;
constexpr int PROJ = 1024;
constexpr int MI = B_ * NI;   // 12800 rows for image-side GEMMs
constexpr int MS = B_ * NS;   // 6400 rows for semantic GEMM

// ---------------- scratch (device globals; no runtime allocation) -------------
__device__ __align__(16) float g_att  [(size_t)B_ * NI * NS];     // 2.56 MB
__device__ __align__(16) float g_sproj[(size_t)MS * PROJ];        // 26 MB
__device__ __align__(16) float g_xcat [(size_t)MI * 2 * PROJ];    // 105 MB
__device__ __align__(16) float g_si[PROJ];
__device__ __align__(16) float g_ss[PROJ];
__device__ __align__(16) float g_sc[OBJ];

// ---------------- row-norm scale: scale[r] = g[r] / ||v[r,:]|| ----------------
__global__ void rownorm_kernel(const float* __restrict__ v, const float* __restrict__ g,
                               float* __restrict__ scale, int K)
{
    int r = blockIdx.x;
    float s = 0.f;
    for (int k = threadIdx.x; k < K; k += blockDim.x) {
        float x = v[(size_t)r * K + k];
        s += x * x;
    }
    __shared__ float red[256];
    red[threadIdx.x] = s;
    __syncthreads();
    #pragma unroll
    for (int o = 128; o > 0; o >>= 1) {
        if (threadIdx.x < o) red[threadIdx.x] += red[threadIdx.x + o];
        __syncthreads();
    }
    if (threadIdx.x == 0) scale[r] = g[r] * rsqrtf(red[0]);
}

// ---------------- attention: softmax over masked pairwise distances -----------
__global__ void att_kernel(const float* __restrict__ pi, const float* __restrict__ ps,
                           const int* __restrict__ mask_s, float* __restrict__ att)
{
    int idx = blockIdx.x * blockDim.x + threadIdx.x;   // b*NI + ni
    if (idx >= B_ * NI) return;
    int b = idx / NI;
    float px = pi[idx * 2 + 0];
    float py = pi[idx * 2 + 1];
    int m = mask_s[b];
    const float* psb = ps + (size_t)b * NS * 2;

    float d[NS];
    float mx = -1e30f;
    #pragma unroll
    for (int j = 0; j < NS; j++) {
        float dx = px - psb[2 * j + 0];
        float dy = py - psb[2 * j + 1];
        d[j] = sqrtf(dx * dx + dy * dy);
        if (j < m) mx = fmaxf(mx, d[j]);
    }
    float sum = 0.f;
    #pragma unroll
    for (int j = 0; j < NS; j++) {
        float e = (j < m) ? __expf(d[j] - mx) : 0.f;
        d[j] = e;
        sum += e;
    }
    float inv = 1.f / sum;
    #pragma unroll
    for (int j = 0; j < NS; j++) att[(size_t)idx * NS + j] = d[j] * inv;
}

// ---------------- batched small matmul: i_att = att @ s_proj ------------------
// grid = (B_, PROJ/128); block = 256
__global__ __launch_bounds__(256) void attmm_kernel(const float* __restrict__ att,
                                                    const float* __restrict__ sproj,
                                                    float* __restrict__ xcat)
{
    __shared__ float at[NI][NS];     // 100 x 50
    __shared__ float sp[NS][128];    //  50 x 128
    int b = blockIdx.x;
    int ncol = blockIdx.y * 128;
    int tid = threadIdx.x;

    for (int e = tid; e < NI * NS; e += 256)
        at[e / NS][e % NS] = att[(size_t)b * NI * NS + e];
    for (int e = tid; e < NS * 128; e += 256) {
        int k = e >> 7, n = e & 127;
        sp[k][n] = sproj[((size_t)b * NS + k) * PROJ + ncol + n];
    }
    __syncthreads();

    int n = tid & 127;
    int mg = tid >> 7;               // 0 or 1 -> rows [0,50) or [50,100)
    for (int m = mg * 50; m < mg * 50 + 50; m++) {
        float acc = 0.f;
        #pragma unroll
        for (int k = 0; k < NS; k++) acc = fmaf(at[m][k], sp[k][n], acc);
        xcat[((size_t)b * NI + m) * (2 * PROJ) + PROJ + ncol + n] = acc;
    }
}

// ---------------- 128x128x8 SGEMM, 8x8 register tile --------------------------
// C[m,n] = epilogue( sum_k A[m,k]*B[n,k] )
// MODE 0: C = relu(acc*scale[n] + bias[n])            (ldc may differ from N)
// MODE 1: C = resid[m,n] + relu(acc*scale[n]+bias[n]) (resid has same ld as C)
// Requirements: M%128==0, N%128==0, lda%4==0, ldb%4==0, ldc%4==0.
template<int MODE>
__global__ __launch_bounds__(256) void sgemm128(
    const float* __restrict__ A, const float* __restrict__ Bm,
    const float* __restrict__ scale, const float* __restrict__ bias,
    const float* __restrict__ resid, float* __restrict__ C,
    int M, int N, int K, int lda, int ldb, int ldc)
{
    __shared__ float As[8][128];
    __shared__ float Bs[8][128];

    int tid = threadIdx.x;
    int tx = tid & 15, ty = tid >> 4;
    int rowBase = blockIdx.y * 128;
    int colBase = blockIdx.x * 128;

    const float* Ablk = A  + (size_t)rowBase * lda;
    const float* Bblk = Bm + (size_t)colBase * ldb;

    float acc[8][8] = {};

    // each thread loads one float4 for A and one for B per k-tile
    int lm = tid >> 1;          // 0..127
    int lk = (tid & 1) * 4;     // 0 or 4

    for (int kt = 0; kt < K; kt += 8) {
        if (kt + 8 <= K) {
            float4 av = *reinterpret_cast<const float4*>(Ablk + (size_t)lm * lda + kt + lk);
            float4 bv = *reinterpret_cast<const float4*>(Bblk + (size_t)lm * ldb + kt + lk);
            As[lk + 0][lm] = av.x; As[lk + 1][lm] = av.y;
            As[lk + 2][lm] = av.z; As[lk + 3][lm] = av.w;
            Bs[lk + 0][lm] = bv.x; Bs[lk + 1][lm] = bv.y;
            Bs[lk + 2][lm] = bv.z; Bs[lk + 3][lm] = bv.w;
        } else {
            #pragma unroll
            for (int u = 0; u < 4; u++) {
                int gk = kt + lk + u;
                As[lk + u][lm] = (gk < K) ? Ablk[(size_t)lm * lda + gk] : 0.f;
                Bs[lk + u][lm] = (gk < K) ? Bblk[(size_t)lm * ldb + gk] : 0.f;
            }
        }
        __syncthreads();

        #pragma unroll
        for (int kk = 0; kk < 8; kk++) {
            float a[8], b[8];
            #pragma unroll
            for (int i = 0; i < 8; i++) a[i] = As[kk][ty * 8 + i];
            #pragma unroll
            for (int j = 0; j < 8; j++) b[j] = Bs[kk][tx * 8 + j];
            #pragma unroll
            for (int i = 0; i < 8; i++)
                #pragma unroll
                for (int j = 0; j < 8; j++)
                    acc[i][j] = fmaf(a[i], b[j], acc[i][j]);
        }
        __syncthreads();
    }

    // epilogue
    #pragma unroll
    for (int i = 0; i < 8; i++) {
        int row = rowBase + ty * 8 + i;
        #pragma unroll
        for (int j = 0; j < 8; j += 4) {
            int col = colBase + tx * 8 + j;
            float4 v;
            float* vp = &v.x;
            #pragma unroll
            for (int u = 0; u < 4; u++) {
                float x = acc[i][j + u] * scale[col + u] + bias[col + u];
                x = fmaxf(x, 0.f);
                if (MODE == 1) x += resid[(size_t)row * ldc + col + u];
                vp[u] = x;
            }
            *reinterpret_cast<float4*>(C + (size_t)row * ldc + col) = v;
        }
    }
}

// ---------------------------------------------------------------------------
extern "C" void kernel_launch(void* const* d_in, const int* in_sizes, int n_in,
                              void* d_out, int out_size)
{
    const float* i_in   = (const float*)d_in[0];
    const float* s_in   = (const float*)d_in[1];
    const float* pi_in  = (const float*)d_in[2];
    const float* ps_in  = (const float*)d_in[3];
    const int*   mask_s = (const int*)  d_in[4];
    const float* vi = (const float*)d_in[5];
    const float* gi = (const float*)d_in[6];
    const float* bi = (const float*)d_in[7];
    const float* vs = (const float*)d_in[8];
    const float* gs = (const float*)d_in[9];
    const float* bs = (const float*)d_in[10];
    const float* vc = (const float*)d_in[11];
    const float* gc = (const float*)d_in[12];
    const float* bc = (const float*)d_in[13];
    float* out = (float*)d_out;

    float *att_p, *sproj_p, *xcat_p, *si_p, *ss_p, *sc_p;
    cudaGetSymbolAddress((void**)&att_p,   g_att);
    cudaGetSymbolAddress((void**)&sproj_p, g_sproj);
    cudaGetSymbolAddress((void**)&xcat_p,  g_xcat);
    cudaGetSymbolAddress((void**)&si_p,    g_si);
    cudaGetSymbolAddress((void**)&ss_p,    g_ss);
    cudaGetSymbolAddress((void**)&sc_p,    g_sc);

    // weight-norm scales
    rownorm_kernel<<<PROJ, 256>>>(vi, gi, si_p, OBJ);
    rownorm_kernel<<<PROJ, 256>>>(vs, gs, ss_p, SEM);
    rownorm_kernel<<<OBJ,  256>>>(vc, gc, sc_p, 2 * PROJ);

    // attention weights
    att_kernel<<<(B_ * NI + 255) / 256, 256>>>(pi_in, ps_in, mask_s, att_p);

    // s_proj = relu_wn(s @ Ws^T):  [6400,300] x [1024,300]^T -> [6400,1024]
    sgemm128<0><<<dim3(PROJ / 128, MS / 128), 256>>>(
        s_in, vs, ss_p, bs, nullptr, sproj_p, MS, PROJ, SEM, SEM, SEM, PROJ);

    // i_proj -> xcat[:, 0:1024]:  [12800,2048] x [1024,2048]^T
    sgemm128<0><<<dim3(PROJ / 128, MI / 128), 256>>>(
        i_in, vi, si_p, bi, nullptr, xcat_p, MI, PROJ, OBJ, OBJ, OBJ, 2 * PROJ);

    // i_att -> xcat[:, 1024:2048]:  batched [100,50]x[50,1024]
    attmm_kernel<<<dim3(B_, PROJ / 128), 256>>>(att_p, sproj_p, xcat_p);

    // out = i + relu_wn(xcat @ Wc^T):  [12800,2048] x [2048,2048]^T
    sgemm128<1><<<dim3(OBJ / 128, MI / 128), 256>>>(
        xcat_p, vc, sc_p, bc, i_in, out, MI, OBJ, 2 * PROJ, 2 * PROJ, 2 * PROJ, OBJ);
}

// round 3
// speedup vs baseline: 4.6645x; 4.6645x over previous
#include <cuda_runtime.h>
#include <cuda_bf16.h>
#include <cstdint>
#include <cstddef>

// Problem constants
constexpr int B_   = 128;
constexpr int NI   = 100;
constexpr int NS   = 50;
constexpr int OBJ  = 2048;
constexpr int SEM  = 300;
constexpr int PROJ = 1024;
constexpr int MI = B_ * NI;   // 12800
constexpr int MS = B_ * NS;   // 6400

// GEMM pipeline config
constexpr int NST = 3;                         // cp.async pipeline stages
constexpr int STAGE_BYTES = 2 * 128 * 32 * 4;  // A + B tile = 32 KB
constexpr int SMEM_DYN = NST * STAGE_BYTES;    // 96 KB

// ---------------- scratch (device globals; no runtime allocation) ------------
__device__ __align__(16) float g_att  [(size_t)B_ * NI * NS];
__device__ __align__(16) float g_sproj[(size_t)MS * PROJ];
__device__ __align__(16) float g_xcat [(size_t)MI * 2 * PROJ];
__device__ __align__(16) float g_i32  [(size_t)MI * OBJ];      // tf32-rounded i
__device__ __align__(16) float g_s32  [(size_t)MS * SEM];      // tf32-rounded s
__device__ __align__(16) float g_vi32 [(size_t)PROJ * OBJ];
__device__ __align__(16) float g_vs32 [(size_t)PROJ * SEM];
__device__ __align__(16) float g_vc32 [(size_t)OBJ * 2 * PROJ];
__device__ __align__(16) float g_si[PROJ];
__device__ __align__(16) float g_ss[PROJ];
__device__ __align__(16) float g_sc[OBJ];

// ======================= helpers ==============================================
__device__ __forceinline__ uint32_t smem_u32(const void* p) {
    uint32_t a;
    asm("{ .reg .u64 t; cvta.to.shared.u64 t, %1; cvt.u32.u64 %0, t; }"
        : "=r"(a) : "l"(p));
    return a;
}
__device__ __forceinline__ float tf32_rn(float x) {
    uint32_t o;
    asm("cvt.rn.tf32.f32 %0, %1;" : "=r"(o) : "f"(x));
    return __uint_as_float(o);
}

// ---------------- tf32 round-copy --------------------------------------------
__global__ void round_copy_kernel(const float* __restrict__ x, float* __restrict__ y,
                                  int n4)
{
    int i = blockIdx.x * blockDim.x + threadIdx.x;
    if (i >= n4) return;
    float4 v = reinterpret_cast<const float4*>(x)[i];
    v.x = tf32_rn(v.x); v.y = tf32_rn(v.y);
    v.z = tf32_rn(v.z); v.w = tf32_rn(v.w);
    reinterpret_cast<float4*>(y)[i] = v;
}

// ---------------- row-norm scale: scale[r] = g[r] / ||v[r,:]|| ----------------
__global__ void rownorm_kernel(const float* __restrict__ v, const float* __restrict__ g,
                               float* __restrict__ scale, int K)
{
    int r = blockIdx.x;
    float s = 0.f;
    for (int k = threadIdx.x; k < K; k += blockDim.x) {
        float x = v[(size_t)r * K + k];
        s += x * x;
    }
    __shared__ float red[256];
    red[threadIdx.x] = s;
    __syncthreads();
    #pragma unroll
    for (int o = 128; o > 0; o >>= 1) {
        if (threadIdx.x < o) red[threadIdx.x] += red[threadIdx.x + o];
        __syncthreads();
    }
    if (threadIdx.x == 0) scale[r] = g[r] * rsqrtf(red[0]);
}

// ---------------- attention: softmax over masked pairwise distances -----------
__global__ void att_kernel(const float* __restrict__ pi, const float* __restrict__ ps,
                           const int* __restrict__ mask_s, float* __restrict__ att)
{
    int idx = blockIdx.x * blockDim.x + threadIdx.x;
    if (idx >= B_ * NI) return;
    int b = idx / NI;
    float px = pi[idx * 2 + 0];
    float py = pi[idx * 2 + 1];
    int m = mask_s[b];
    const float* psb = ps + (size_t)b * NS * 2;

    float d[NS];
    float mx = -1e30f;
    #pragma unroll
    for (int j = 0; j < NS; j++) {
        float dx = px - psb[2 * j + 0];
        float dy = py - psb[2 * j + 1];
        d[j] = sqrtf(dx * dx + dy * dy);
        if (j < m) mx = fmaxf(mx, d[j]);
    }
    float sum = 0.f;
    #pragma unroll
    for (int j = 0; j < NS; j++) {
        float e = (j < m) ? __expf(d[j] - mx) : 0.f;
        d[j] = e;
        sum += e;
    }
    float inv = 1.f / sum;
    #pragma unroll
    for (int j = 0; j < NS; j++) att[(size_t)idx * NS + j] = d[j] * inv;
}

// ---------------- batched small matmul: i_att = att @ s_proj ------------------
__global__ __launch_bounds__(256) void attmm_kernel(const float* __restrict__ att,
                                                    const float* __restrict__ sproj,
                                                    float* __restrict__ xcat)
{
    __shared__ float at[NI][NS];
    __shared__ float sp[NS][128];
    int b = blockIdx.x;
    int ncol = blockIdx.y * 128;
    int tid = threadIdx.x;

    for (int e = tid; e < NI * NS; e += 256)
        at[e / NS][e % NS] = att[(size_t)b * NI * NS + e];
    for (int e = tid; e < NS * 128; e += 256) {
        int k = e >> 7, n = e & 127;
        sp[k][n] = sproj[((size_t)b * NS + k) * PROJ + ncol + n];
    }
    __syncthreads();

    int n = tid & 127;
    int mg = tid >> 7;
    for (int m = mg * 50; m < mg * 50 + 50; m++) {
        float acc = 0.f;
        #pragma unroll
        for (int k = 0; k < NS; k++) acc = fmaf(at[m][k], sp[k][n], acc);
        xcat[((size_t)b * NI + m) * (2 * PROJ) + PROJ + ncol + n] = tf32_rn(acc);
    }
}

// ================ tf32 mma.sync GEMM: C = epi(A[M,K] @ B[N,K]^T) ==============
// 128x128 CTA tile, 8 warps in 2x4 grid, warp tile 64x32 of m16n8k8 MMAs.
// MODE 0: C = relu(acc*scale[n]+bias[n])    MODE 1: += resid[m,n]
// ROUND:  RN-round stored values to tf32.
// A,B operands are expected pre-rounded to tf32 bit patterns.
template<int MODE, bool ROUND>
__global__ __launch_bounds__(256, 2) void gemm_mma(
    const float* __restrict__ A, const float* __restrict__ Bm,
    const float* __restrict__ scale, const float* __restrict__ bias,
    const float* __restrict__ resid, float* __restrict__ C,
    int K, int lda, int ldb, int ldc)
{
    extern __shared__ __align__(128) char dynsmem[];
    const uint32_t sbase = smem_u32(dynsmem);
    const int tid  = threadIdx.x;
    const int lane = tid & 31;
    const int wid  = tid >> 5;
    const int wm   = wid >> 2;   // 0..1  (warp row)
    const int wn   = wid & 3;    // 0..3  (warp col)
    const int rowBase = blockIdx.y * 128;
    const int colBase = blockIdx.x * 128;

    const float* Ablk = A  + (size_t)rowBase * lda;
    const float* Bblk = Bm + (size_t)colBase * ldb;
    const int KT = (K + 31) / 32;

    // ---- loader: 128x32 A tile + 128x32 B tile into stage, XOR-swizzled ------
    auto load_chunk = [&](int L) {
        const int s = L % NST;
        const int k0 = L * 32;
        const uint32_t stage = sbase + s * STAGE_BYTES;
        const bool tail = (k0 + 32 > K);
        #pragma unroll
        for (int it = 0; it < 8; ++it) {
            int t = tid + it * 256;            // 0..2047
            int which = t >> 10;               // 0=A, 1=B
            int r = (t >> 3) & 127;
            int j = t & 7;                     // 16B chunk within 128B row
            int gk = k0 + j * 4;
            const float* src = (which ? Bblk + (size_t)r * ldb
                                      : Ablk + (size_t)r * lda) + gk;
            uint32_t dst = stage + which * 16384 + r * 128 + ((j ^ (r & 7)) << 4);
            if (!tail) {
                asm volatile("cp.async.cg.shared.global [%0], [%1], 16;"
                             :: "r"(dst), "l"(src) : "memory");
            } else {
                float x0 = (gk + 0 < K) ? src[0] : 0.f;
                float x1 = (gk + 1 < K) ? src[1] : 0.f;
                float x2 = (gk + 2 < K) ? src[2] : 0.f;
                float x3 = (gk + 3 < K) ? src[3] : 0.f;
                asm volatile("st.shared.v4.f32 [%0], {%1,%2,%3,%4};"
                             :: "r"(dst), "f"(x0), "f"(x1), "f"(x2), "f"(x3) : "memory");
            }
        }
    };

    // ---- prologue ------------------------------------------------------------
    #pragma unroll
    for (int p = 0; p < NST - 1; ++p) {
        if (p < KT) load_chunk(p);
        asm volatile("cp.async.commit_group;" ::: "memory");
    }

    float acc[4][4][4];
    #pragma unroll
    for (int a = 0; a < 4; a++)
        #pragma unroll
        for (int b = 0; b < 4; b++)
            #pragma unroll
            for (int c = 0; c < 4; c++) acc[a][b][c] = 0.f;

    // ---- main loop -------------------------------------------------------------
    for (int c = 0; c < KT; ++c) {
        asm volatile("cp.async.wait_group 1;" ::: "memory");  // chunk c resident
        __syncthreads();                                       // + prev compute done

        const int L = c + NST - 1;
        if (L < KT) load_chunk(L);
        asm volatile("cp.async.commit_group;" ::: "memory");

        const uint32_t ast = sbase + (c % NST) * STAGE_BYTES;
        const uint32_t bst = ast + 16384;

        #pragma unroll
        for (int ks = 0; ks < 4; ++ks) {
            uint32_t af[4][4], bf[4][2];
            // A fragments: 4 m-tiles of 16 rows
            #pragma unroll
            for (int mt = 0; mt < 4; ++mt) {
                int r = wm * 64 + mt * 16 + (lane & 7) + ((lane & 8) ? 8 : 0);
                int ch = ks * 2 + (lane >> 4);
                uint32_t addr = ast + r * 128 + ((ch ^ (r & 7)) << 4);
                asm volatile("ldmatrix.sync.aligned.m8n8.x4.shared.b16 "
                             "{%0,%1,%2,%3}, [%4];"
                             : "=r"(af[mt][0]), "=r"(af[mt][1]),
                               "=r"(af[mt][2]), "=r"(af[mt][3])
                             : "r"(addr));
            }
            // B fragments: 4 n-tiles of 8 cols, 2 tiles per ldmatrix.x4
            #pragma unroll
            for (int np = 0; np < 2; ++np) {
                int tile = np * 2 + (lane >> 4);
                int half = (lane >> 3) & 1;
                int r = wn * 32 + tile * 8 + (lane & 7);
                int ch = ks * 2 + half;
                uint32_t addr = bst + r * 128 + ((ch ^ (r & 7)) << 4);
                asm volatile("ldmatrix.sync.aligned.m8n8.x4.shared.b16 "
                             "{%0,%1,%2,%3}, [%4];"
                             : "=r"(bf[np * 2][0]), "=r"(bf[np * 2][1]),
                               "=r"(bf[np * 2 + 1][0]), "=r"(bf[np * 2 + 1][1])
                             : "r"(addr));
            }
            // 4x4 m16n8k8 MMAs
            #pragma unroll
            for (int mt = 0; mt < 4; ++mt)
                #pragma unroll
                for (int nt = 0; nt < 4; ++nt) {
                    asm volatile(
                        "mma.sync.aligned.m16n8k8.row.col.f32.tf32.tf32.f32 "
                        "{%0,%1,%2,%3}, {%4,%5,%6,%7}, {%8,%9}, {%0,%1,%2,%3};"
                        : "+f"(acc[mt][nt][0]), "+f"(acc[mt][nt][1]),
                          "+f"(acc[mt][nt][2]), "+f"(acc[mt][nt][3])
                        : "r"(af[mt][0]), "r"(af[mt][1]),
                          "r"(af[mt][2]), "r"(af[mt][3]),
                          "r"(bf[nt][0]), "r"(bf[nt][1]));
                }
        }
    }

    // ---- epilogue ----------------------------------------------------------------
    #pragma unroll
    for (int mt = 0; mt < 4; ++mt) {
        int r0 = rowBase + wm * 64 + mt * 16 + (lane >> 2);
        #pragma unroll
        for (int nt = 0; nt < 4; ++nt) {
            int col = colBase + wn * 32 + nt * 8 + (lane & 3) * 2;
            float2 sc = *reinterpret_cast<const float2*>(scale + col);
            float2 bi = *reinterpret_cast<const float2*>(bias + col);
            #pragma unroll
            for (int h = 0; h < 2; ++h) {                   // rows r0, r0+8
                int row = r0 + h * 8;
                float2 o;
                o.x = fmaxf(acc[mt][nt][h * 2 + 0] * sc.x + bi.x, 0.f);
                o.y = fmaxf(acc[mt][nt][h * 2 + 1] * sc.y + bi.y, 0.f);
                if (ROUND) { o.x = tf32_rn(o.x); o.y = tf32_rn(o.y); }
                if (MODE == 1) {
                    float2 rr = *reinterpret_cast<const float2*>(
                        resid + (size_t)row * ldc + col);
                    o.x += rr.x; o.y += rr.y;
                }
                *reinterpret_cast<float2*>(C + (size_t)row * ldc + col) = o;
            }
        }
    }
}

// ---------------------------------------------------------------------------
extern "C" void kernel_launch(void* const* d_in, const int* in_sizes, int n_in,
                              void* d_out, int out_size)
{
    const float* i_in   = (const float*)d_in[0];
    const float* s_in   = (const float*)d_in[1];
    const float* pi_in  = (const float*)d_in[2];
    const float* ps_in  = (const float*)d_in[3];
    const int*   mask_s = (const int*)  d_in[4];
    const float* vi = (const float*)d_in[5];
    const float* gi = (const float*)d_in[6];
    const float* bi = (const float*)d_in[7];
    const float* vs = (const float*)d_in[8];
    const float* gs = (const float*)d_in[9];
    const float* bs = (const float*)d_in[10];
    const float* vc = (const float*)d_in[11];
    const float* gc = (const float*)d_in[12];
    const float* bc = (const float*)d_in[13];
    float* out = (float*)d_out;

    float *att_p, *sproj_p, *xcat_p, *si_p, *ss_p, *sc_p;
    float *i32_p, *s32_p, *vi32_p, *vs32_p, *vc32_p;
    cudaGetSymbolAddress((void**)&att_p,   g_att);
    cudaGetSymbolAddress((void**)&sproj_p, g_sproj);
    cudaGetSymbolAddress((void**)&xcat_p,  g_xcat);
    cudaGetSymbolAddress((void**)&si_p,    g_si);
    cudaGetSymbolAddress((void**)&ss_p,    g_ss);
    cudaGetSymbolAddress((void**)&sc_p,    g_sc);
    cudaGetSymbolAddress((void**)&i32_p,   g_i32);
    cudaGetSymbolAddress((void**)&s32_p,   g_s32);
    cudaGetSymbolAddress((void**)&vi32_p,  g_vi32);
    cudaGetSymbolAddress((void**)&vs32_p,  g_vs32);
    cudaGetSymbolAddress((void**)&vc32_p,  g_vc32);

    cudaFuncSetAttribute(gemm_mma<0, true >, cudaFuncAttributeMaxDynamicSharedMemorySize, SMEM_DYN);
    cudaFuncSetAttribute(gemm_mma<1, false>, cudaFuncAttributeMaxDynamicSharedMemorySize, SMEM_DYN);

    auto rc = [&](const float* src, float* dst, size_t n) {
        int n4 = (int)(n / 4);
        round_copy_kernel<<<(n4 + 255) / 256, 256>>>(src, dst, n4);
    };

    // tf32 pre-rounded operand copies
    rc(i_in, i32_p,  (size_t)MI * OBJ);
    rc(s_in, s32_p,  (size_t)MS * SEM);
    rc(vi,   vi32_p, (size_t)PROJ * OBJ);
    rc(vs,   vs32_p, (size_t)PROJ * SEM);
    rc(vc,   vc32_p, (size_t)OBJ * 2 * PROJ);

    // weight-norm scales (from full-precision weights)
    rownorm_kernel<<<PROJ, 256>>>(vi, gi, si_p, OBJ);
    rownorm_kernel<<<PROJ, 256>>>(vs, gs, ss_p, SEM);
    rownorm_kernel<<<OBJ,  256>>>(vc, gc, sc_p, 2 * PROJ);

    // attention weights
    att_kernel<<<(B_ * NI + 255) / 256, 256>>>(pi_in, ps_in, mask_s, att_p);

    // s_proj = relu_wn(s @ Ws^T): [6400,300] x [1024,300]^T  (round for attmm/tf32)
    gemm_mma<0, true><<<dim3(PROJ / 128, MS / 128), 256, SMEM_DYN>>>(
        s32_p, vs32_p, ss_p, bs, nullptr, sproj_p, SEM, SEM, SEM, PROJ);

    // i_proj -> xcat[:, 0:1024]: [12800,2048] x [1024,2048]^T  (rounded)
    gemm_mma<0, true><<<dim3(PROJ / 128, MI / 128), 256, SMEM_DYN>>>(
        i32_p, vi32_p, si_p, bi, nullptr, xcat_p, OBJ, OBJ, OBJ, 2 * PROJ);

    // i_att -> xcat[:, 1024:2048]: batched [100,50]x[50,1024]  (rounded)
    attmm_kernel<<<dim3(B_, PROJ / 128), 256>>>(att_p, sproj_p, xcat_p);

    // out = i + relu_wn(xcat @ Wc^T): [12800,2048] x [2048,2048]^T
    gemm_mma<1, false><<<dim3(OBJ / 128, MI / 128), 256, SMEM_DYN>>>(
        xcat_p, vc32_p, sc_p, bc, i_in, out, 2 * PROJ, 2 * PROJ, 2 * PROJ, OBJ);
}

// round 4
// speedup vs baseline: 4.9302x; 1.0570x over previous
#include <cuda_runtime.h>
#include <cuda_bf16.h>
#include <cstdint>
#include <cstddef>

// Problem constants
constexpr int B_   = 128;
constexpr int NI   = 100;
constexpr int NS   = 50;
constexpr int OBJ  = 2048;
constexpr int SEM  = 300;
constexpr int PROJ = 1024;
constexpr int MI = B_ * NI;   // 12800
constexpr int MS = B_ * NS;   // 6400

// GEMM pipeline config
constexpr int NST = 3;                         // cp.async pipeline stages
constexpr int STAGE_BYTES = 2 * 128 * 32 * 4;  // A + B tile = 32 KB
constexpr int SMEM_DYN = NST * STAGE_BYTES;    // 96 KB

// ---------------- scratch (device globals; no runtime allocation) ------------
__device__ __align__(16) float g_att  [(size_t)B_ * NI * NS];
__device__ __align__(16) float g_sproj[(size_t)MS * PROJ];
__device__ __align__(16) float g_xcat [(size_t)MI * 2 * PROJ];
__device__ __align__(16) float g_s32  [(size_t)MS * SEM];      // tf32-rounded s
__device__ __align__(16) float g_vi32 [(size_t)PROJ * OBJ];
__device__ __align__(16) float g_vs32 [(size_t)PROJ * SEM];
__device__ __align__(16) float g_vc32 [(size_t)OBJ * 2 * PROJ];
__device__ __align__(16) float g_si[PROJ];
__device__ __align__(16) float g_ss[PROJ];
__device__ __align__(16) float g_sc[OBJ];

// ======================= helpers ==============================================
__device__ __forceinline__ uint32_t smem_u32(const void* p) {
    uint32_t a;
    asm("{ .reg .u64 t; cvta.to.shared.u64 t, %1; cvt.u32.u64 %0, t; }"
        : "=r"(a) : "l"(p));
    return a;
}
__device__ __forceinline__ float tf32_rn(float x) {
    uint32_t o;
    asm("cvt.rn.tf32.f32 %0, %1;" : "=r"(o) : "f"(x));
    return __uint_as_float(o);
}

// ---------------- fused tf32 round-copy of the 4 operand buffers ---------------
constexpr int RC_N1 = MS * SEM / 4;        // s
constexpr int RC_N2 = PROJ * OBJ / 4;      // vi
constexpr int RC_N3 = PROJ * SEM / 4;      // vs
constexpr int RC_N4 = OBJ * 2 * PROJ / 4;  // vc
constexpr int RC_TOT = RC_N1 + RC_N2 + RC_N3 + RC_N4;

__global__ void prep_round_kernel(const float* __restrict__ s,  float* __restrict__ s32,
                                  const float* __restrict__ vi, float* __restrict__ vi32,
                                  const float* __restrict__ vs, float* __restrict__ vs32,
                                  const float* __restrict__ vc, float* __restrict__ vc32)
{
    for (int i = blockIdx.x * blockDim.x + threadIdx.x; i < RC_TOT;
         i += gridDim.x * blockDim.x) {
        const float* src; float* dst; int j = i;
        if (j < RC_N1)                    { src = s;  dst = s32; }
        else if ((j -= RC_N1) < RC_N2)    { src = vi; dst = vi32; }
        else if ((j -= RC_N2) < RC_N3)    { src = vs; dst = vs32; }
        else { j -= RC_N3;                  src = vc; dst = vc32; }
        float4 v = reinterpret_cast<const float4*>(src)[j];
        v.x = tf32_rn(v.x); v.y = tf32_rn(v.y);
        v.z = tf32_rn(v.z); v.w = tf32_rn(v.w);
        reinterpret_cast<float4*>(dst)[j] = v;
    }
}

// ---------------- fused row-norm scales: scale[r] = g[r] / ||v[r,:]|| ----------
__global__ void rownorm_all_kernel(const float* __restrict__ vi, const float* __restrict__ gi,
                                   float* __restrict__ si,
                                   const float* __restrict__ vs, const float* __restrict__ gs,
                                   float* __restrict__ ss,
                                   const float* __restrict__ vc, const float* __restrict__ gc,
                                   float* __restrict__ sc)
{
    int blk = blockIdx.x;
    const float *v, *g; float* out; int K, r;
    if (blk < PROJ)            { v = vi; g = gi; out = si; K = OBJ;      r = blk; }
    else if (blk < 2 * PROJ)   { v = vs; g = gs; out = ss; K = SEM;      r = blk - PROJ; }
    else                       { v = vc; g = gc; out = sc; K = 2 * PROJ; r = blk - 2 * PROJ; }

    float s = 0.f;
    for (int k = threadIdx.x; k < K; k += blockDim.x) {
        float x = v[(size_t)r * K + k];
        s += x * x;
    }
    __shared__ float red[256];
    red[threadIdx.x] = s;
    __syncthreads();
    #pragma unroll
    for (int o = 128; o > 0; o >>= 1) {
        if (threadIdx.x < o) red[threadIdx.x] += red[threadIdx.x + o];
        __syncthreads();
    }
    if (threadIdx.x == 0) out[r] = g[r] * rsqrtf(red[0]);
}

// ---------------- attention: softmax over masked pairwise distances -----------
__global__ void att_kernel(const float* __restrict__ pi, const float* __restrict__ ps,
                           const int* __restrict__ mask_s, float* __restrict__ att)
{
    int idx = blockIdx.x * blockDim.x + threadIdx.x;
    if (idx >= B_ * NI) return;
    int b = idx / NI;
    float px = pi[idx * 2 + 0];
    float py = pi[idx * 2 + 1];
    int m = mask_s[b];
    const float* psb = ps + (size_t)b * NS * 2;

    float d[NS];
    float mx = -1e30f;
    #pragma unroll
    for (int j = 0; j < NS; j++) {
        float dx = px - psb[2 * j + 0];
        float dy = py - psb[2 * j + 1];
        d[j] = sqrtf(dx * dx + dy * dy);
        if (j < m) mx = fmaxf(mx, d[j]);
    }
    float sum = 0.f;
    #pragma unroll
    for (int j = 0; j < NS; j++) {
        float e = (j < m) ? __expf(d[j] - mx) : 0.f;
        d[j] = e;
        sum += e;
    }
    float inv = 1.f / sum;
    #pragma unroll
    for (int j = 0; j < NS; j++) att[(size_t)idx * NS + j] = d[j] * inv;
}

// ---------------- batched small matmul: i_att = att @ s_proj ------------------
__global__ __launch_bounds__(256) void attmm_kernel(const float* __restrict__ att,
                                                    const float* __restrict__ sproj,
                                                    float* __restrict__ xcat)
{
    __shared__ float at[NI][NS];
    __shared__ float sp[NS][128];
    int b = blockIdx.x;
    int ncol = blockIdx.y * 128;
    int tid = threadIdx.x;

    for (int e = tid; e < NI * NS; e += 256)
        at[e / NS][e % NS] = att[(size_t)b * NI * NS + e];
    for (int e = tid; e < NS * 128; e += 256) {
        int k = e >> 7, n = e & 127;
        sp[k][n] = sproj[((size_t)b * NS + k) * PROJ + ncol + n];
    }
    __syncthreads();

    int n = tid & 127;
    int mg = tid >> 7;
    for (int m = mg * 50; m < mg * 50 + 50; m++) {
        float acc = 0.f;
        #pragma unroll
        for (int k = 0; k < NS; k++) acc = fmaf(at[m][k], sp[k][n], acc);
        xcat[((size_t)b * NI + m) * (2 * PROJ) + PROJ + ncol + n] = tf32_rn(acc);
    }
}

// ================ tf32 mma.sync GEMM: C = epi(A[M,K] @ B[N,K]^T) ==============
// 128x128 CTA tile, 8 warps in 2x4 grid, warp tile 64x32 of m16n8k8 MMAs.
// MODE 0: C = relu(acc*scale[n]+bias[n])    MODE 1: += resid[m,n]
// ROUND:  RN-round stored values to tf32.
template<int MODE, bool ROUND>
__global__ __launch_bounds__(256, 2) void gemm_mma(
    const float* __restrict__ A, const float* __restrict__ Bm,
    const float* __restrict__ scale, const float* __restrict__ bias,
    const float* __restrict__ resid, float* __restrict__ C,
    int K, int lda, int ldb, int ldc)
{
    extern __shared__ __align__(128) char dynsmem[];
    const uint32_t sbase = smem_u32(dynsmem);
    const int tid  = threadIdx.x;
    const int lane = tid & 31;
    const int wid  = tid >> 5;
    const int wm   = wid >> 2;   // 0..1  (warp row)
    const int wn   = wid & 3;    // 0..3  (warp col)
    const int rowBase = blockIdx.y * 128;
    const int colBase = blockIdx.x * 128;

    const float* Ablk = A  + (size_t)rowBase * lda;
    const float* Bblk = Bm + (size_t)colBase * ldb;
    const int KT = (K + 31) / 32;

    // ---- loader: 128x32 A tile + 128x32 B tile into stage, XOR-swizzled ------
    auto load_chunk = [&](int L) {
        const int s = L % NST;
        const int k0 = L * 32;
        const uint32_t stage = sbase + s * STAGE_BYTES;
        const bool tail = (k0 + 32 > K);
        #pragma unroll
        for (int it = 0; it < 8; ++it) {
            int t = tid + it * 256;            // 0..2047
            int which = t >> 10;               // 0=A, 1=B
            int r = (t >> 3) & 127;
            int j = t & 7;                     // 16B chunk within 128B row
            int gk = k0 + j * 4;
            const float* src = (which ? Bblk + (size_t)r * ldb
                                      : Ablk + (size_t)r * lda) + gk;
            uint32_t dst = stage + which * 16384 + r * 128 + ((j ^ (r & 7)) << 4);
            if (!tail) {
                asm volatile("cp.async.cg.shared.global [%0], [%1], 16;"
                             :: "r"(dst), "l"(src) : "memory");
            } else {
                float x0 = (gk + 0 < K) ? src[0] : 0.f;
                float x1 = (gk + 1 < K) ? src[1] : 0.f;
                float x2 = (gk + 2 < K) ? src[2] : 0.f;
                float x3 = (gk + 3 < K) ? src[3] : 0.f;
                asm volatile("st.shared.v4.f32 [%0], {%1,%2,%3,%4};"
                             :: "r"(dst), "f"(x0), "f"(x1), "f"(x2), "f"(x3) : "memory");
            }
        }
    };

    // ---- prologue ------------------------------------------------------------
    #pragma unroll
    for (int p = 0; p < NST - 1; ++p) {
        if (p < KT) load_chunk(p);
        asm volatile("cp.async.commit_group;" ::: "memory");
    }

    float acc[4][4][4];
    #pragma unroll
    for (int a = 0; a < 4; a++)
        #pragma unroll
        for (int b = 0; b < 4; b++)
            #pragma unroll
            for (int c = 0; c < 4; c++) acc[a][b][c] = 0.f;

    // ---- main loop -------------------------------------------------------------
    for (int c = 0; c < KT; ++c) {
        asm volatile("cp.async.wait_group 1;" ::: "memory");  // chunk c resident
        __syncthreads();                                       // + prev compute done

        const int L = c + NST - 1;
        if (L < KT) load_chunk(L);
        asm volatile("cp.async.commit_group;" ::: "memory");

        const uint32_t ast = sbase + (c % NST) * STAGE_BYTES;
        const uint32_t bst = ast + 16384;

        #pragma unroll
        for (int ks = 0; ks < 4; ++ks) {
            uint32_t af[4][4], bf[4][2];
            // A fragments: 4 m-tiles of 16 rows
            #pragma unroll
            for (int mt = 0; mt < 4; ++mt) {
                int r = wm * 64 + mt * 16 + (lane & 7) + ((lane & 8) ? 8 : 0);
                int ch = ks * 2 + (lane >> 4);
                uint32_t addr = ast + r * 128 + ((ch ^ (r & 7)) << 4);
                asm volatile("ldmatrix.sync.aligned.m8n8.x4.shared.b16 "
                             "{%0,%1,%2,%3}, [%4];"
                             : "=r"(af[mt][0]), "=r"(af[mt][1]),
                               "=r"(af[mt][2]), "=r"(af[mt][3])
                             : "r"(addr));
            }
            // B fragments: 4 n-tiles of 8 cols, 2 tiles per ldmatrix.x4
            #pragma unroll
            for (int np = 0; np < 2; ++np) {
                int tile = np * 2 + (lane >> 4);
                int half = (lane >> 3) & 1;
                int r = wn * 32 + tile * 8 + (lane & 7);
                int ch = ks * 2 + half;
                uint32_t addr = bst + r * 128 + ((ch ^ (r & 7)) << 4);
                asm volatile("ldmatrix.sync.aligned.m8n8.x4.shared.b16 "
                             "{%0,%1,%2,%3}, [%4];"
                             : "=r"(bf[np * 2][0]), "=r"(bf[np * 2][1]),
                               "=r"(bf[np * 2 + 1][0]), "=r"(bf[np * 2 + 1][1])
                             : "r"(addr));
            }
            // 4x4 m16n8k8 MMAs
            #pragma unroll
            for (int mt = 0; mt < 4; ++mt)
                #pragma unroll
                for (int nt = 0; nt < 4; ++nt) {
                    asm volatile(
                        "mma.sync.aligned.m16n8k8.row.col.f32.tf32.tf32.f32 "
                        "{%0,%1,%2,%3}, {%4,%5,%6,%7}, {%8,%9}, {%0,%1,%2,%3};"
                        : "+f"(acc[mt][nt][0]), "+f"(acc[mt][nt][1]),
                          "+f"(acc[mt][nt][2]), "+f"(acc[mt][nt][3])
                        : "r"(af[mt][0]), "r"(af[mt][1]),
                          "r"(af[mt][2]), "r"(af[mt][3]),
                          "r"(bf[nt][0]), "r"(bf[nt][1]));
                }
        }
    }

    // ---- epilogue ----------------------------------------------------------------
    #pragma unroll
    for (int mt = 0; mt < 4; ++mt) {
        int r0 = rowBase + wm * 64 + mt * 16 + (lane >> 2);
        #pragma unroll
        for (int nt = 0; nt < 4; ++nt) {
            int col = colBase + wn * 32 + nt * 8 + (lane & 3) * 2;
            float2 sc = *reinterpret_cast<const float2*>(scale + col);
            float2 bi = *reinterpret_cast<const float2*>(bias + col);
            #pragma unroll
            for (int h = 0; h < 2; ++h) {                   // rows r0, r0+8
                int row = r0 + h * 8;
                float2 o;
                o.x = fmaxf(acc[mt][nt][h * 2 + 0] * sc.x + bi.x, 0.f);
                o.y = fmaxf(acc[mt][nt][h * 2 + 1] * sc.y + bi.y, 0.f);
                if (ROUND) { o.x = tf32_rn(o.x); o.y = tf32_rn(o.y); }
                if (MODE == 1) {
                    float2 rr = *reinterpret_cast<const float2*>(
                        resid + (size_t)row * ldc + col);
                    o.x += rr.x; o.y += rr.y;
                }
                *reinterpret_cast<float2*>(C + (size_t)row * ldc + col) = o;
            }
        }
    }
}

// ---------------------------------------------------------------------------
extern "C" void kernel_launch(void* const* d_in, const int* in_sizes, int n_in,
                              void* d_out, int out_size)
{
    const float* i_in   = (const float*)d_in[0];
    const float* s_in   = (const float*)d_in[1];
    const float* pi_in  = (const float*)d_in[2];
    const float* ps_in  = (const float*)d_in[3];
    const int*   mask_s = (const int*)  d_in[4];
    const float* vi = (const float*)d_in[5];
    const float* gi = (const float*)d_in[6];
    const float* bi = (const float*)d_in[7];
    const float* vs = (const float*)d_in[8];
    const float* gs = (const float*)d_in[9];
    const float* bs = (const float*)d_in[10];
    const float* vc = (const float*)d_in[11];
    const float* gc = (const float*)d_in[12];
    const float* bc = (const float*)d_in[13];
    float* out = (float*)d_out;

    float *att_p, *sproj_p, *xcat_p, *si_p, *ss_p, *sc_p;
    float *s32_p, *vi32_p, *vs32_p, *vc32_p;
    cudaGetSymbolAddress((void**)&att_p,   g_att);
    cudaGetSymbolAddress((void**)&sproj_p, g_sproj);
    cudaGetSymbolAddress((void**)&xcat_p,  g_xcat);
    cudaGetSymbolAddress((void**)&si_p,    g_si);
    cudaGetSymbolAddress((void**)&ss_p,    g_ss);
    cudaGetSymbolAddress((void**)&sc_p,    g_sc);
    cudaGetSymbolAddress((void**)&s32_p,   g_s32);
    cudaGetSymbolAddress((void**)&vi32_p,  g_vi32);
    cudaGetSymbolAddress((void**)&vs32_p,  g_vs32);
    cudaGetSymbolAddress((void**)&vc32_p,  g_vc32);

    cudaFuncSetAttribute(gemm_mma<0, true >, cudaFuncAttributeMaxDynamicSharedMemorySize, SMEM_DYN);
    cudaFuncSetAttribute(gemm_mma<1, false>, cudaFuncAttributeMaxDynamicSharedMemorySize, SMEM_DYN);

    // launch 0: tf32 pre-rounding of s + weights (fused)
    prep_round_kernel<<<1184, 256>>>(s_in, s32_p, vi, vi32_p, vs, vs32_p, vc, vc32_p);

    // launch 1: weight-norm scales (fused; full-precision weights)
    rownorm_all_kernel<<<2 * PROJ + OBJ, 256>>>(vi, gi, si_p, vs, gs, ss_p, vc, gc, sc_p);

    // launch 2: attention weights
    att_kernel<<<(B_ * NI + 255) / 256, 256>>>(pi_in, ps_in, mask_s, att_p);

    // launch 3: s_proj = relu_wn(s @ Ws^T): [6400,300] x [1024,300]^T
    gemm_mma<0, true><<<dim3(PROJ / 128, MS / 128), 256, SMEM_DYN>>>(
        s32_p, vs32_p, ss_p, bs, nullptr, sproj_p, SEM, SEM, SEM, PROJ);

    // launch 4: i_att -> xcat[:, 1024:2048]: batched [100,50]x[50,1024]
    attmm_kernel<<<dim3(B_, PROJ / 128), 256>>>(att_p, sproj_p, xcat_p);

    // launch 5 (ncu -s 5 target): i_proj -> xcat[:, 0:1024]
    // A = raw i (HW tf32 truncation on A only; B pre-rounded)
    gemm_mma<0, true><<<dim3(PROJ / 128, MI / 128), 256, SMEM_DYN>>>(
        i_in, vi32_p, si_p, bi, nullptr, xcat_p, OBJ, OBJ, OBJ, 2 * PROJ);

    // launch 6: out = i + relu_wn(xcat @ Wc^T): [12800,2048] x [2048,2048]^T
    gemm_mma<1, false><<<dim3(OBJ / 128, MI / 128), 256, SMEM_DYN>>>(
        xcat_p, vc32_p, sc_p, bc, i_in, out, 2 * PROJ, 2 * PROJ, 2 * PROJ, OBJ);
}

// round 5
// speedup vs baseline: 7.7890x; 1.5799x over previous
#include <cuda_runtime.h>
#include <cuda_fp16.h>
#include <cstdint>
#include <cstddef>

// Problem constants
constexpr int B_   = 128;
constexpr int NI   = 100;
constexpr int NS   = 50;
constexpr int OBJ  = 2048;
constexpr int SEM  = 300;
constexpr int SEMP = 304;   // padded lda for fp16 s/vs (16B-aligned rows)
constexpr int PROJ = 1024;
constexpr int MI = B_ * NI;   // 12800
constexpr int MS = B_ * NS;   // 6400

// GEMM pipeline config (fp16): chunk = 64 k, tile row = 128 bytes
constexpr int NST = 3;
constexpr int STAGE_BYTES = 2 * 128 * 128;     // A tile 16KB + B tile 16KB
constexpr int SMEM_DYN = NST * STAGE_BYTES;    // 96 KB

// ---------------- scratch (device globals; no runtime allocation) ------------
__device__ __align__(16) float  g_att  [(size_t)B_ * NI * NS];
__device__ __align__(16) __half g_sproj[(size_t)MS * PROJ];
__device__ __align__(16) __half g_xcat [(size_t)MI * 2 * PROJ];
__device__ __align__(16) __half g_i16  [(size_t)MI * OBJ];
__device__ __align__(16) __half g_s16  [(size_t)MS * SEMP];
__device__ __align__(16) __half g_vi16 [(size_t)PROJ * OBJ];
__device__ __align__(16) __half g_vs16 [(size_t)PROJ * SEMP];
__device__ __align__(16) __half g_vc16 [(size_t)OBJ * 2 * PROJ];
__device__ __align__(16) float  g_si[PROJ];
__device__ __align__(16) float  g_ss[PROJ];
__device__ __align__(16) float  g_sc[OBJ];

// ======================= helpers ==============================================
__device__ __forceinline__ uint32_t smem_u32(const void* p) {
    uint32_t a;
    asm("{ .reg .u64 t; cvta.to.shared.u64 t, %1; cvt.u32.u64 %0, t; }"
        : "=r"(a) : "l"(p));
    return a;
}

// ---------------- fused fp16 convert of the 5 GEMM operand buffers ------------
// Dense buffers (4-elem vectorized): i, vi, vc.  Padded buffers: s, vs.
constexpr int CV_NI = MI * OBJ / 4;
constexpr int CV_NVI = PROJ * OBJ / 4;
constexpr int CV_NVC = OBJ * 2 * PROJ / 4;
constexpr int CV_DENSE = CV_NI + CV_NVI + CV_NVC;
constexpr int CV_NS = MS * SEM / 4;        // s rows: 300/4 = 75 vec4 per row
constexpr int CV_NVS = PROJ * SEM / 4;
constexpr int CV_TOT = CV_DENSE + CV_NS + CV_NVS;

__global__ void prep_convert_kernel(const float* __restrict__ i_in, __half* __restrict__ i16,
                                    const float* __restrict__ vi,   __half* __restrict__ vi16,
                                    const float* __restrict__ vc,   __half* __restrict__ vc16,
                                    const float* __restrict__ s,    __half* __restrict__ s16,
                                    const float* __restrict__ vs,   __half* __restrict__ vs16)
{
    for (int t = blockIdx.x * blockDim.x + threadIdx.x; t < CV_TOT;
         t += gridDim.x * blockDim.x) {
        const float* src; __half* dst; int j = t, dj;
        if (j < CV_NI)                      { src = i_in; dst = i16;  dj = j; }
        else if ((j -= CV_NI) < CV_NVI)     { src = vi;   dst = vi16; dj = j; }
        else if ((j -= CV_NVI) < CV_NVC)    { src = vc;   dst = vc16; dj = j; }
        else if ((j -= CV_NVC) < CV_NS) {
            src = s;  dst = s16;
            int row = j / 75, c = j % 75;                // 75 vec4 per 300-row
            dj = -1;                                      // custom store below
            float4 v = reinterpret_cast<const float4*>(src)[j];
            __half2* d = reinterpret_cast<__half2*>(dst + (size_t)row * SEMP + c * 4);
            d[0] = __floats2half2_rn(v.x, v.y);
            d[1] = __floats2half2_rn(v.z, v.w);
            continue;
        } else {
            j -= CV_NS;
            src = vs; dst = vs16;
            int row = j / 75, c = j % 75;
            float4 v = reinterpret_cast<const float4*>(src)[j];
            __half2* d = reinterpret_cast<__half2*>(dst + (size_t)row * SEMP + c * 4);
            d[0] = __floats2half2_rn(v.x, v.y);
            d[1] = __floats2half2_rn(v.z, v.w);
            continue;
        }
        float4 v = reinterpret_cast<const float4*>(src)[dj];
        __half2* d = reinterpret_cast<__half2*>(dst + (size_t)dj * 4);
        d[0] = __floats2half2_rn(v.x, v.y);
        d[1] = __floats2half2_rn(v.z, v.w);
    }
}

// ---------------- fused row-norm scales: scale[r] = g[r] / ||v[r,:]|| ----------
__global__ void rownorm_all_kernel(const float* __restrict__ vi, const float* __restrict__ gi,
                                   float* __restrict__ si,
                                   const float* __restrict__ vs, const float* __restrict__ gs,
                                   float* __restrict__ ss,
                                   const float* __restrict__ vc, const float* __restrict__ gc,
                                   float* __restrict__ sc)
{
    int blk = blockIdx.x;
    const float *v, *g; float* out; int K, r;
    if (blk < PROJ)            { v = vi; g = gi; out = si; K = OBJ;      r = blk; }
    else if (blk < 2 * PROJ)   { v = vs; g = gs; out = ss; K = SEM;      r = blk - PROJ; }
    else                       { v = vc; g = gc; out = sc; K = 2 * PROJ; r = blk - 2 * PROJ; }

    float s = 0.f;
    for (int k = threadIdx.x; k < K; k += blockDim.x) {
        float x = v[(size_t)r * K + k];
        s += x * x;
    }
    __shared__ float red[256];
    red[threadIdx.x] = s;
    __syncthreads();
    #pragma unroll
    for (int o = 128; o > 0; o >>= 1) {
        if (threadIdx.x < o) red[threadIdx.x] += red[threadIdx.x + o];
        __syncthreads();
    }
    if (threadIdx.x == 0) out[r] = g[r] * rsqrtf(red[0]);
}

// ---------------- attention: softmax over masked pairwise distances -----------
__global__ void att_kernel(const float* __restrict__ pi, const float* __restrict__ ps,
                           const int* __restrict__ mask_s, float* __restrict__ att)
{
    int idx = blockIdx.x * blockDim.x + threadIdx.x;
    if (idx >= B_ * NI) return;
    int b = idx / NI;
    float px = pi[idx * 2 + 0];
    float py = pi[idx * 2 + 1];
    int m = mask_s[b];
    const float* psb = ps + (size_t)b * NS * 2;

    float d[NS];
    float mx = -1e30f;
    #pragma unroll
    for (int j = 0; j < NS; j++) {
        float dx = px - psb[2 * j + 0];
        float dy = py - psb[2 * j + 1];
        d[j] = sqrtf(dx * dx + dy * dy);
        if (j < m) mx = fmaxf(mx, d[j]);
    }
    float sum = 0.f;
    #pragma unroll
    for (int j = 0; j < NS; j++) {
        float e = (j < m) ? __expf(d[j] - mx) : 0.f;
        d[j] = e;
        sum += e;
    }
    float inv = 1.f / sum;
    #pragma unroll
    for (int j = 0; j < NS; j++) att[(size_t)idx * NS + j] = d[j] * inv;
}

// ---------------- batched small matmul: i_att = att @ s_proj ------------------
__global__ __launch_bounds__(256) void attmm_kernel(const float* __restrict__ att,
                                                    const __half* __restrict__ sproj,
                                                    __half* __restrict__ xcat)
{
    __shared__ float at[NI][NS];
    __shared__ float sp[NS][128];
    int b = blockIdx.x;
    int ncol = blockIdx.y * 128;
    int tid = threadIdx.x;

    for (int e = tid; e < NI * NS; e += 256)
        at[e / NS][e % NS] = att[(size_t)b * NI * NS + e];
    for (int e = tid; e < NS * 128; e += 256) {
        int k = e >> 7, n = e & 127;
        sp[k][n] = __half2float(sproj[((size_t)b * NS + k) * PROJ + ncol + n]);
    }
    __syncthreads();

    int n = tid & 127;
    int mg = tid >> 7;
    for (int m = mg * 50; m < mg * 50 + 50; m++) {
        float acc = 0.f;
        #pragma unroll
        for (int k = 0; k < NS; k++) acc = fmaf(at[m][k], sp[k][n], acc);
        xcat[((size_t)b * NI + m) * (2 * PROJ) + PROJ + ncol + n] = __float2half_rn(acc);
    }
}

// ================ fp16 mma.sync GEMM: C = epi(A[M,K] @ B[N,K]^T) ==============
// 128x128 CTA tile, 8 warps (2x4), warp tile 64x32 of m16n8k16 MMAs, K-chunk 64.
// MODE 0: C(half) = relu(acc*scale[n]+bias[n])
// MODE 1: C(float) = resid[m,n] + relu(acc*scale[n]+bias[n])
template<int MODE>
__global__ __launch_bounds__(256, 2) void gemm_mma_h(
    const __half* __restrict__ A, const __half* __restrict__ Bm,
    const float* __restrict__ scale, const float* __restrict__ bias,
    const float* __restrict__ resid, void* __restrict__ Cv,
    int K, int lda, int ldb, int ldc)
{
    extern __shared__ __align__(128) char dynsmem[];
    const uint32_t sbase = smem_u32(dynsmem);
    const int tid  = threadIdx.x;
    const int lane = tid & 31;
    const int wid  = tid >> 5;
    const int wm   = wid >> 2;   // 0..1
    const int wn   = wid & 3;    // 0..3
    const int rowBase = blockIdx.y * 128;
    const int colBase = blockIdx.x * 128;

    const __half* Ablk = A  + (size_t)rowBase * lda;
    const __half* Bblk = Bm + (size_t)colBase * ldb;
    const int KT = (K + 63) / 64;

    // ---- loader: 128x64h A tile + 128x64h B tile into stage, XOR-swizzled ----
    auto load_chunk = [&](int L) {
        const int s = L % NST;
        const int k0 = L * 64;
        const uint32_t stage = sbase + s * STAGE_BYTES;
        const bool tail = (k0 + 64 > K);
        #pragma unroll
        for (int it = 0; it < 8; ++it) {
            int t = tid + it * 256;            // 0..2047
            int which = t >> 10;               // 0=A, 1=B
            int r = (t >> 3) & 127;
            int j = t & 7;                     // 16B chunk within 128B row
            int gk = k0 + j * 8;               // 8 halves per chunk
            const __half* src = (which ? Bblk + (size_t)r * ldb
                                       : Ablk + (size_t)r * lda) + gk;
            uint32_t dst = stage + which * 16384 + r * 128 + ((j ^ (r & 7)) << 4);
            if (!tail) {
                asm volatile("cp.async.cg.shared.global [%0], [%1], 16;"
                             :: "r"(dst), "l"(src) : "memory");
            } else {
                uint32_t w[4];
                #pragma unroll
                for (int u = 0; u < 4; ++u) {
                    __half lo = (gk + 2 * u     < K) ? src[2 * u]     : __half(0.f);
                    __half hi = (gk + 2 * u + 1 < K) ? src[2 * u + 1] : __half(0.f);
                    __half2 h2 = __halves2half2(lo, hi);
                    w[u] = *reinterpret_cast<uint32_t*>(&h2);
                }
                asm volatile("st.shared.v4.b32 [%0], {%1,%2,%3,%4};"
                             :: "r"(dst), "r"(w[0]), "r"(w[1]), "r"(w[2]), "r"(w[3])
                             : "memory");
            }
        }
    };

    // ---- prologue ------------------------------------------------------------
    #pragma unroll
    for (int p = 0; p < NST - 1; ++p) {
        if (p < KT) load_chunk(p);
        asm volatile("cp.async.commit_group;" ::: "memory");
    }

    float acc[4][4][4];
    #pragma unroll
    for (int a = 0; a < 4; a++)
        #pragma unroll
        for (int b = 0; b < 4; b++)
            #pragma unroll
            for (int c = 0; c < 4; c++) acc[a][b][c] = 0.f;

    // ---- main loop -------------------------------------------------------------
    for (int c = 0; c < KT; ++c) {
        asm volatile("cp.async.wait_group 1;" ::: "memory");
        __syncthreads();

        const int L = c + NST - 1;
        if (L < KT) load_chunk(L);
        asm volatile("cp.async.commit_group;" ::: "memory");

        const uint32_t ast = sbase + (c % NST) * STAGE_BYTES;
        const uint32_t bst = ast + 16384;

        #pragma unroll
        for (int ks = 0; ks < 4; ++ks) {               // 4 x k16 per 64-chunk
            uint32_t af[4][4], bf[4][2];
            // A fragments: 4 m-tiles of 16 rows, k16 slice ks
            #pragma unroll
            for (int mt = 0; mt < 4; ++mt) {
                int r = wm * 64 + mt * 16 + (lane & 15);
                int ch = ks * 2 + (lane >> 4);
                uint32_t addr = ast + r * 128 + ((ch ^ (r & 7)) << 4);
                asm volatile("ldmatrix.sync.aligned.m8n8.x4.shared.b16 "
                             "{%0,%1,%2,%3}, [%4];"
                             : "=r"(af[mt][0]), "=r"(af[mt][1]),
                               "=r"(af[mt][2]), "=r"(af[mt][3])
                             : "r"(addr));
            }
            // B fragments: 4 n-tiles of 8 cols, 2 tiles per ldmatrix.x4
            #pragma unroll
            for (int np = 0; np < 2; ++np) {
                int tile = np * 2 + (lane >> 4);
                int half_k = (lane >> 3) & 1;
                int r = wn * 32 + tile * 8 + (lane & 7);
                int ch = ks * 2 + half_k;
                uint32_t addr = bst + r * 128 + ((ch ^ (r & 7)) << 4);
                asm volatile("ldmatrix.sync.aligned.m8n8.x4.shared.b16 "
                             "{%0,%1,%2,%3}, [%4];"
                             : "=r"(bf[np * 2][0]), "=r"(bf[np * 2][1]),
                               "=r"(bf[np * 2 + 1][0]), "=r"(bf[np * 2 + 1][1])
                             : "r"(addr));
            }
            // 4x4 m16n8k16 MMAs
            #pragma unroll
            for (int mt = 0; mt < 4; ++mt)
                #pragma unroll
                for (int nt = 0; nt < 4; ++nt) {
                    asm volatile(
                        "mma.sync.aligned.m16n8k16.row.col.f32.f16.f16.f32 "
                        "{%0,%1,%2,%3}, {%4,%5,%6,%7}, {%8,%9}, {%0,%1,%2,%3};"
                        : "+f"(acc[mt][nt][0]), "+f"(acc[mt][nt][1]),
                          "+f"(acc[mt][nt][2]), "+f"(acc[mt][nt][3])
                        : "r"(af[mt][0]), "r"(af[mt][1]),
                          "r"(af[mt][2]), "r"(af[mt][3]),
                          "r"(bf[nt][0]), "r"(bf[nt][1]));
                }
        }
    }

    // ---- epilogue ----------------------------------------------------------------
    #pragma unroll
    for (int mt = 0; mt < 4; ++mt) {
        int r0 = rowBase + wm * 64 + mt * 16 + (lane >> 2);
        #pragma unroll
        for (int nt = 0; nt < 4; ++nt) {
            int col = colBase + wn * 32 + nt * 8 + (lane & 3) * 2;
            float2 sc = *reinterpret_cast<const float2*>(scale + col);
            float2 bi = *reinterpret_cast<const float2*>(bias + col);
            #pragma unroll
            for (int h = 0; h < 2; ++h) {
                int row = r0 + h * 8;
                float ox = fmaxf(acc[mt][nt][h * 2 + 0] * sc.x + bi.x, 0.f);
                float oy = fmaxf(acc[mt][nt][h * 2 + 1] * sc.y + bi.y, 0.f);
                if (MODE == 0) {
                    __half* C = (__half*)Cv;
                    *reinterpret_cast<__half2*>(C + (size_t)row * ldc + col) =
                        __floats2half2_rn(ox, oy);
                } else {
                    float* C = (float*)Cv;
                    float2 rr = *reinterpret_cast<const float2*>(
                        resid + (size_t)row * ldc + col);
                    float2 o = {ox + rr.x, oy + rr.y};
                    *reinterpret_cast<float2*>(C + (size_t)row * ldc + col) = o;
                }
            }
        }
    }
}

// ---------------------------------------------------------------------------
extern "C" void kernel_launch(void* const* d_in, const int* in_sizes, int n_in,
                              void* d_out, int out_size)
{
    const float* i_in   = (const float*)d_in[0];
    const float* s_in   = (const float*)d_in[1];
    const float* pi_in  = (const float*)d_in[2];
    const float* ps_in  = (const float*)d_in[3];
    const int*   mask_s = (const int*)  d_in[4];
    const float* vi = (const float*)d_in[5];
    const float* gi = (const float*)d_in[6];
    const float* bi = (const float*)d_in[7];
    const float* vs = (const float*)d_in[8];
    const float* gs = (const float*)d_in[9];
    const float* bs = (const float*)d_in[10];
    const float* vc = (const float*)d_in[11];
    const float* gc = (const float*)d_in[12];
    const float* bc = (const float*)d_in[13];
    float* out = (float*)d_out;

    float *att_p, *si_p, *ss_p, *sc_p;
    __half *sproj_p, *xcat_p, *i16_p, *s16_p, *vi16_p, *vs16_p, *vc16_p;
    cudaGetSymbolAddress((void**)&att_p,   g_att);
    cudaGetSymbolAddress((void**)&sproj_p, g_sproj);
    cudaGetSymbolAddress((void**)&xcat_p,  g_xcat);
    cudaGetSymbolAddress((void**)&si_p,    g_si);
    cudaGetSymbolAddress((void**)&ss_p,    g_ss);
    cudaGetSymbolAddress((void**)&sc_p,    g_sc);
    cudaGetSymbolAddress((void**)&i16_p,   g_i16);
    cudaGetSymbolAddress((void**)&s16_p,   g_s16);
    cudaGetSymbolAddress((void**)&vi16_p,  g_vi16);
    cudaGetSymbolAddress((void**)&vs16_p,  g_vs16);
    cudaGetSymbolAddress((void**)&vc16_p,  g_vc16);

    cudaFuncSetAttribute(gemm_mma_h<0>, cudaFuncAttributeMaxDynamicSharedMemorySize, SMEM_DYN);
    cudaFuncSetAttribute(gemm_mma_h<1>, cudaFuncAttributeMaxDynamicSharedMemorySize, SMEM_DYN);

    // launch 0: fp16 conversion of all GEMM operands (fused)
    prep_convert_kernel<<<4096, 256>>>(i_in, i16_p, vi, vi16_p, vc, vc16_p,
                                       s_in, s16_p, vs, vs16_p);

    // launch 1: weight-norm scales (fused; full-precision weights)
    rownorm_all_kernel<<<2 * PROJ + OBJ, 256>>>(vi, gi, si_p, vs, gs, ss_p, vc, gc, sc_p);

    // launch 2: attention weights
    att_kernel<<<(B_ * NI + 255) / 256, 256>>>(pi_in, ps_in, mask_s, att_p);

    // launch 3: s_proj = relu_wn(s @ Ws^T): [6400,300] x [1024,300]^T -> half
    gemm_mma_h<0><<<dim3(PROJ / 128, MS / 128), 256, SMEM_DYN>>>(
        s16_p, vs16_p, ss_p, bs, nullptr, sproj_p, SEM, SEMP, SEMP, PROJ);

    // launch 4: i_att -> xcat[:, 1024:2048]: batched [100,50]x[50,1024]
    attmm_kernel<<<dim3(B_, PROJ / 128), 256>>>(att_p, sproj_p, xcat_p);

    // launch 5 (ncu -s 5 target): i_proj -> xcat[:, 0:1024]
    gemm_mma_h<0><<<dim3(PROJ / 128, MI / 128), 256, SMEM_DYN>>>(
        i16_p, vi16_p, si_p, bi, nullptr, xcat_p, OBJ, OBJ, OBJ, 2 * PROJ);

    // launch 6: out = i + relu_wn(xcat @ Wc^T): [12800,2048] x [2048,2048]^T
    gemm_mma_h<1><<<dim3(OBJ / 128, MI / 128), 256, SMEM_DYN>>>(
        xcat_p, vc16_p, sc_p, bc, i_in, out, 2 * PROJ, 2 * PROJ, 2 * PROJ, OBJ);
}

// round 6
// speedup vs baseline: 7.7922x; 1.0004x over previous
#include <cuda_runtime.h>
#include <cuda_fp16.h>
#include <cstdint>
#include <cstddef>

// Problem constants
constexpr int B_   = 128;
constexpr int NI   = 100;
constexpr int NS   = 50;
constexpr int OBJ  = 2048;
constexpr int SEM  = 300;
constexpr int SEMP = 304;   // padded lda for fp16 s/vs (16B-aligned rows)
constexpr int PROJ = 1024;
constexpr int MI = B_ * NI;   // 12800
constexpr int MS = B_ * NS;   // 6400

// 128x128 GEMM pipeline (for the small s_proj GEMM)
constexpr int NST = 3;
constexpr int STAGE_BYTES = 2 * 128 * 128;     // A 16KB + B 16KB
constexpr int SMEM_DYN = NST * STAGE_BYTES;    // 96 KB

// 256x128 GEMM pipeline (big GEMMs)
constexpr int NST2 = 3;
constexpr int STAGE2_BYTES = (256 + 128) * 128;   // A 32KB + B 16KB = 48KB
constexpr int SMEM_DYN2 = NST2 * STAGE2_BYTES;    // 144 KB

// ---------------- scratch (device globals; no runtime allocation) ------------
__device__ __align__(16) float  g_att  [(size_t)B_ * NI * NS];
__device__ __align__(16) __half g_sproj[(size_t)MS * PROJ];
__device__ __align__(16) __half g_xcat [(size_t)MI * 2 * PROJ];
__device__ __align__(16) __half g_i16  [(size_t)MI * OBJ];
__device__ __align__(16) __half g_s16  [(size_t)MS * SEMP];
__device__ __align__(16) __half g_vi16 [(size_t)PROJ * OBJ];
__device__ __align__(16) __half g_vs16 [(size_t)PROJ * SEMP];
__device__ __align__(16) __half g_vc16 [(size_t)OBJ * 2 * PROJ];
__device__ __align__(16) float  g_si[PROJ];
__device__ __align__(16) float  g_ss[PROJ];
__device__ __align__(16) float  g_sc[OBJ];

// ======================= helpers ==============================================
__device__ __forceinline__ uint32_t smem_u32(const void* p) {
    uint32_t a;
    asm("{ .reg .u64 t; cvta.to.shared.u64 t, %1; cvt.u32.u64 %0, t; }"
        : "=r"(a) : "l"(p));
    return a;
}

// ---------------- fused fp16 convert of the 5 GEMM operand buffers ------------
constexpr int CV_NI = MI * OBJ / 4;
constexpr int CV_NVI = PROJ * OBJ / 4;
constexpr int CV_NVC = OBJ * 2 * PROJ / 4;
constexpr int CV_DENSE = CV_NI + CV_NVI + CV_NVC;
constexpr int CV_NS = MS * SEM / 4;
constexpr int CV_NVS = PROJ * SEM / 4;
constexpr int CV_TOT = CV_DENSE + CV_NS + CV_NVS;

__global__ void prep_convert_kernel(const float* __restrict__ i_in, __half* __restrict__ i16,
                                    const float* __restrict__ vi,   __half* __restrict__ vi16,
                                    const float* __restrict__ vc,   __half* __restrict__ vc16,
                                    const float* __restrict__ s,    __half* __restrict__ s16,
                                    const float* __restrict__ vs,   __half* __restrict__ vs16)
{
    for (int t = blockIdx.x * blockDim.x + threadIdx.x; t < CV_TOT;
         t += gridDim.x * blockDim.x) {
        const float* src; __half* dst; int j = t, dj;
        if (j < CV_NI)                      { src = i_in; dst = i16;  dj = j; }
        else if ((j -= CV_NI) < CV_NVI)     { src = vi;   dst = vi16; dj = j; }
        else if ((j -= CV_NVI) < CV_NVC)    { src = vc;   dst = vc16; dj = j; }
        else if ((j -= CV_NVC) < CV_NS) {
            src = s;  dst = s16;
            int row = j / 75, c = j % 75;
            float4 v = reinterpret_cast<const float4*>(src)[j];
            __half2* d = reinterpret_cast<__half2*>(dst + (size_t)row * SEMP + c * 4);
            d[0] = __floats2half2_rn(v.x, v.y);
            d[1] = __floats2half2_rn(v.z, v.w);
            continue;
        } else {
            j -= CV_NS;
            src = vs; dst = vs16;
            int row = j / 75, c = j % 75;
            float4 v = reinterpret_cast<const float4*>(src)[j];
            __half2* d = reinterpret_cast<__half2*>(dst + (size_t)row * SEMP + c * 4);
            d[0] = __floats2half2_rn(v.x, v.y);
            d[1] = __floats2half2_rn(v.z, v.w);
            continue;
        }
        float4 v = reinterpret_cast<const float4*>(src)[dj];
        __half2* d = reinterpret_cast<__half2*>(dst + (size_t)dj * 4);
        d[0] = __floats2half2_rn(v.x, v.y);
        d[1] = __floats2half2_rn(v.z, v.w);
    }
}

// ---------------- fused row-norm scales ---------------------------------------
__global__ void rownorm_all_kernel(const float* __restrict__ vi, const float* __restrict__ gi,
                                   float* __restrict__ si,
                                   const float* __restrict__ vs, const float* __restrict__ gs,
                                   float* __restrict__ ss,
                                   const float* __restrict__ vc, const float* __restrict__ gc,
                                   float* __restrict__ sc)
{
    int blk = blockIdx.x;
    const float *v, *g; float* out; int K, r;
    if (blk < PROJ)            { v = vi; g = gi; out = si; K = OBJ;      r = blk; }
    else if (blk < 2 * PROJ)   { v = vs; g = gs; out = ss; K = SEM;      r = blk - PROJ; }
    else                       { v = vc; g = gc; out = sc; K = 2 * PROJ; r = blk - 2 * PROJ; }

    float s = 0.f;
    for (int k = threadIdx.x; k < K; k += blockDim.x) {
        float x = v[(size_t)r * K + k];
        s += x * x;
    }
    __shared__ float red[256];
    red[threadIdx.x] = s;
    __syncthreads();
    #pragma unroll
    for (int o = 128; o > 0; o >>= 1) {
        if (threadIdx.x < o) red[threadIdx.x] += red[threadIdx.x + o];
        __syncthreads();
    }
    if (threadIdx.x == 0) out[r] = g[r] * rsqrtf(red[0]);
}

// ---------------- attention softmax -------------------------------------------
__global__ void att_kernel(const float* __restrict__ pi, const float* __restrict__ ps,
                           const int* __restrict__ mask_s, float* __restrict__ att)
{
    int idx = blockIdx.x * blockDim.x + threadIdx.x;
    if (idx >= B_ * NI) return;
    int b = idx / NI;
    float px = pi[idx * 2 + 0];
    float py = pi[idx * 2 + 1];
    int m = mask_s[b];
    const float* psb = ps + (size_t)b * NS * 2;

    float d[NS];
    float mx = -1e30f;
    #pragma unroll
    for (int j = 0; j < NS; j++) {
        float dx = px - psb[2 * j + 0];
        float dy = py - psb[2 * j + 1];
        d[j] = sqrtf(dx * dx + dy * dy);
        if (j < m) mx = fmaxf(mx, d[j]);
    }
    float sum = 0.f;
    #pragma unroll
    for (int j = 0; j < NS; j++) {
        float e = (j < m) ? __expf(d[j] - mx) : 0.f;
        d[j] = e;
        sum += e;
    }
    float inv = 1.f / sum;
    #pragma unroll
    for (int j = 0; j < NS; j++) att[(size_t)idx * NS + j] = d[j] * inv;
}

// ---------------- batched small matmul: i_att = att @ s_proj ------------------
__global__ __launch_bounds__(256) void attmm_kernel(const float* __restrict__ att,
                                                    const __half* __restrict__ sproj,
                                                    __half* __restrict__ xcat)
{
    __shared__ float at[NI][NS];
    __shared__ float sp[NS][128];
    int b = blockIdx.x;
    int ncol = blockIdx.y * 128;
    int tid = threadIdx.x;

    for (int e = tid; e < NI * NS; e += 256)
        at[e / NS][e % NS] = att[(size_t)b * NI * NS + e];
    for (int e = tid; e < NS * 128; e += 256) {
        int k = e >> 7, n = e & 127;
        sp[k][n] = __half2float(sproj[((size_t)b * NS + k) * PROJ + ncol + n]);
    }
    __syncthreads();

    int n = tid & 127;
    int mg = tid >> 7;
    for (int m = mg * 50; m < mg * 50 + 50; m++) {
        float acc = 0.f;
        #pragma unroll
        for (int k = 0; k < NS; k++) acc = fmaf(at[m][k], sp[k][n], acc);
        xcat[((size_t)b * NI + m) * (2 * PROJ) + PROJ + ncol + n] = __float2half_rn(acc);
    }
}

// ================ fp16 GEMM 128x128 (used for s_proj; handles K tails) ========
template<int MODE>
__global__ __launch_bounds__(256, 2) void gemm_mma_h(
    const __half* __restrict__ A, const __half* __restrict__ Bm,
    const float* __restrict__ scale, const float* __restrict__ bias,
    const float* __restrict__ resid, void* __restrict__ Cv,
    int K, int lda, int ldb, int ldc)
{
    extern __shared__ __align__(128) char dynsmem[];
    const uint32_t sbase = smem_u32(dynsmem);
    const int tid  = threadIdx.x;
    const int lane = tid & 31;
    const int wid  = tid >> 5;
    const int wm   = wid >> 2;
    const int wn   = wid & 3;
    const int rowBase = blockIdx.y * 128;
    const int colBase = blockIdx.x * 128;

    const __half* Ablk = A  + (size_t)rowBase * lda;
    const __half* Bblk = Bm + (size_t)colBase * ldb;
    const int KT = (K + 63) / 64;

    auto load_chunk = [&](int L) {
        const int s = L % NST;
        const int k0 = L * 64;
        const uint32_t stage = sbase + s * STAGE_BYTES;
        const bool tail = (k0 + 64 > K);
        #pragma unroll
        for (int it = 0; it < 8; ++it) {
            int t = tid + it * 256;
            int which = t >> 10;
            int r = (t >> 3) & 127;
            int j = t & 7;
            int gk = k0 + j * 8;
            const __half* src = (which ? Bblk + (size_t)r * ldb
                                       : Ablk + (size_t)r * lda) + gk;
            uint32_t dst = stage + which * 16384 + r * 128 + ((j ^ (r & 7)) << 4);
            if (!tail) {
                asm volatile("cp.async.cg.shared.global [%0], [%1], 16;"
                             :: "r"(dst), "l"(src) : "memory");
            } else {
                uint32_t w[4];
                #pragma unroll
                for (int u = 0; u < 4; ++u) {
                    __half lo = (gk + 2 * u     < K) ? src[2 * u]     : __half(0.f);
                    __half hi = (gk + 2 * u + 1 < K) ? src[2 * u + 1] : __half(0.f);
                    __half2 h2 = __halves2half2(lo, hi);
                    w[u] = *reinterpret_cast<uint32_t*>(&h2);
                }
                asm volatile("st.shared.v4.b32 [%0], {%1,%2,%3,%4};"
                             :: "r"(dst), "r"(w[0]), "r"(w[1]), "r"(w[2]), "r"(w[3])
                             : "memory");
            }
        }
    };

    #pragma unroll
    for (int p = 0; p < NST - 1; ++p) {
        if (p < KT) load_chunk(p);
        asm volatile("cp.async.commit_group;" ::: "memory");
    }

    float acc[4][4][4];
    #pragma unroll
    for (int a = 0; a < 4; a++)
        #pragma unroll
        for (int b = 0; b < 4; b++)
            #pragma unroll
            for (int c = 0; c < 4; c++) acc[a][b][c] = 0.f;

    for (int c = 0; c < KT; ++c) {
        asm volatile("cp.async.wait_group 1;" ::: "memory");
        __syncthreads();

        const int L = c + NST - 1;
        if (L < KT) load_chunk(L);
        asm volatile("cp.async.commit_group;" ::: "memory");

        const uint32_t ast = sbase + (c % NST) * STAGE_BYTES;
        const uint32_t bst = ast + 16384;

        #pragma unroll
        for (int ks = 0; ks < 4; ++ks) {
            uint32_t af[4][4], bf[4][2];
            #pragma unroll
            for (int mt = 0; mt < 4; ++mt) {
                int r = wm * 64 + mt * 16 + (lane & 15);
                int ch = ks * 2 + (lane >> 4);
                uint32_t addr = ast + r * 128 + ((ch ^ (r & 7)) << 4);
                asm volatile("ldmatrix.sync.aligned.m8n8.x4.shared.b16 "
                             "{%0,%1,%2,%3}, [%4];"
                             : "=r"(af[mt][0]), "=r"(af[mt][1]),
                               "=r"(af[mt][2]), "=r"(af[mt][3])
                             : "r"(addr));
            }
            #pragma unroll
            for (int np = 0; np < 2; ++np) {
                int tile = np * 2 + (lane >> 4);
                int half_k = (lane >> 3) & 1;
                int r = wn * 32 + tile * 8 + (lane & 7);
                int ch = ks * 2 + half_k;
                uint32_t addr = bst + r * 128 + ((ch ^ (r & 7)) << 4);
                asm volatile("ldmatrix.sync.aligned.m8n8.x4.shared.b16 "
                             "{%0,%1,%2,%3}, [%4];"
                             : "=r"(bf[np * 2][0]), "=r"(bf[np * 2][1]),
                               "=r"(bf[np * 2 + 1][0]), "=r"(bf[np * 2 + 1][1])
                             : "r"(addr));
            }
            #pragma unroll
            for (int mt = 0; mt < 4; ++mt)
                #pragma unroll
                for (int nt = 0; nt < 4; ++nt) {
                    asm volatile(
                        "mma.sync.aligned.m16n8k16.row.col.f32.f16.f16.f32 "
                        "{%0,%1,%2,%3}, {%4,%5,%6,%7}, {%8,%9}, {%0,%1,%2,%3};"
                        : "+f"(acc[mt][nt][0]), "+f"(acc[mt][nt][1]),
                          "+f"(acc[mt][nt][2]), "+f"(acc[mt][nt][3])
                        : "r"(af[mt][0]), "r"(af[mt][1]),
                          "r"(af[mt][2]), "r"(af[mt][3]),
                          "r"(bf[nt][0]), "r"(bf[nt][1]));
                }
        }
    }

    #pragma unroll
    for (int mt = 0; mt < 4; ++mt) {
        int r0 = rowBase + wm * 64 + mt * 16 + (lane >> 2);
        #pragma unroll
        for (int nt = 0; nt < 4; ++nt) {
            int col = colBase + wn * 32 + nt * 8 + (lane & 3) * 2;
            float2 sc = *reinterpret_cast<const float2*>(scale + col);
            float2 bi = *reinterpret_cast<const float2*>(bias + col);
            #pragma unroll
            for (int h = 0; h < 2; ++h) {
                int row = r0 + h * 8;
                float ox = fmaxf(acc[mt][nt][h * 2 + 0] * sc.x + bi.x, 0.f);
                float oy = fmaxf(acc[mt][nt][h * 2 + 1] * sc.y + bi.y, 0.f);
                if (MODE == 0) {
                    __half* C = (__half*)Cv;
                    *reinterpret_cast<__half2*>(C + (size_t)row * ldc + col) =
                        __floats2half2_rn(ox, oy);
                } else {
                    float* C = (float*)Cv;
                    float2 rr = *reinterpret_cast<const float2*>(
                        resid + (size_t)row * ldc + col);
                    float2 o = {ox + rr.x, oy + rr.y};
                    *reinterpret_cast<float2*>(C + (size_t)row * ldc + col) = o;
                }
            }
        }
    }
}

// ================ fp16 GEMM 256x128 (big GEMMs; K % 64 == 0) ==================
// 8 warps in 4x2 grid, warp tile 64x64 (4 m-tiles x 8 n-tiles of m16n8k16).
// MODE 0: C(half) = relu(acc*scale+bias)   MODE 1: C(float) = resid + relu(...)
template<int MODE>
__global__ __launch_bounds__(256, 1) void gemm_mma_h2(
    const __half* __restrict__ A, const __half* __restrict__ Bm,
    const float* __restrict__ scale, const float* __restrict__ bias,
    const float* __restrict__ resid, void* __restrict__ Cv,
    int K, int lda, int ldb, int ldc)
{
    extern __shared__ __align__(128) char dynsmem[];
    const uint32_t sbase = smem_u32(dynsmem);
    const int tid  = threadIdx.x;
    const int lane = tid & 31;
    const int wid  = tid >> 5;
    const int wm   = wid >> 1;   // 0..3  (warp row, 64 rows each)
    const int wn   = wid & 1;    // 0..1  (warp col, 64 cols each)
    const int rowBase = blockIdx.y * 256;
    const int colBase = blockIdx.x * 128;

    const __half* Ablk = A  + (size_t)rowBase * lda;
    const __half* Bblk = Bm + (size_t)colBase * ldb;
    const int KT = K / 64;

    // A tile: 256 rows x 128B (32KB); B tile: 128 rows x 128B (16KB)
    auto load_chunk = [&](int L) {
        const int s = L % NST2;
        const int k0 = L * 64;
        const uint32_t stage = sbase + s * STAGE2_BYTES;
        #pragma unroll
        for (int it = 0; it < 12; ++it) {
            int t = tid + it * 256;            // 0..3071
            bool isB = t >= 2048;
            int tt = isB ? t - 2048 : t;
            int r = tt >> 3;                   // A: 0..255, B: 0..127
            int j = tt & 7;
            int gk = k0 + j * 8;
            const __half* src = (isB ? Bblk + (size_t)r * ldb
                                     : Ablk + (size_t)r * lda) + gk;
            uint32_t dst = stage + (isB ? 32768 : 0) + r * 128 + ((j ^ (r & 7)) << 4);
            asm volatile("cp.async.cg.shared.global [%0], [%1], 16;"
                         :: "r"(dst), "l"(src) : "memory");
        }
    };

    #pragma unroll
    for (int p = 0; p < NST2 - 1; ++p) {
        if (p < KT) load_chunk(p);
        asm volatile("cp.async.commit_group;" ::: "memory");
    }

    float acc[4][8][4];
    #pragma unroll
    for (int a = 0; a < 4; a++)
        #pragma unroll
        for (int b = 0; b < 8; b++)
            #pragma unroll
            for (int c = 0; c < 4; c++) acc[a][b][c] = 0.f;

    for (int c = 0; c < KT; ++c) {
        asm volatile("cp.async.wait_group 1;" ::: "memory");
        __syncthreads();

        const int L = c + NST2 - 1;
        if (L < KT) load_chunk(L);
        asm volatile("cp.async.commit_group;" ::: "memory");

        const uint32_t ast = sbase + (c % NST2) * STAGE2_BYTES;
        const uint32_t bst = ast + 32768;

        #pragma unroll
        for (int ks = 0; ks < 4; ++ks) {
            uint32_t af[4][4], bf[8][2];
            // A fragments: 4 m-tiles of 16 rows
            #pragma unroll
            for (int mt = 0; mt < 4; ++mt) {
                int r = wm * 64 + mt * 16 + (lane & 15);
                int ch = ks * 2 + (lane >> 4);
                uint32_t addr = ast + r * 128 + ((ch ^ (r & 7)) << 4);
                asm volatile("ldmatrix.sync.aligned.m8n8.x4.shared.b16 "
                             "{%0,%1,%2,%3}, [%4];"
                             : "=r"(af[mt][0]), "=r"(af[mt][1]),
                               "=r"(af[mt][2]), "=r"(af[mt][3])
                             : "r"(addr));
            }
            // B fragments: 8 n-tiles of 8 cols, 2 tiles per ldmatrix.x4
            #pragma unroll
            for (int np = 0; np < 4; ++np) {
                int tile = np * 2 + (lane >> 4);
                int half_k = (lane >> 3) & 1;
                int r = wn * 64 + tile * 8 + (lane & 7);
                int ch = ks * 2 + half_k;
                uint32_t addr = bst + r * 128 + ((ch ^ (r & 7)) << 4);
                asm volatile("ldmatrix.sync.aligned.m8n8.x4.shared.b16 "
                             "{%0,%1,%2,%3}, [%4];"
                             : "=r"(bf[np * 2][0]), "=r"(bf[np * 2][1]),
                               "=r"(bf[np * 2 + 1][0]), "=r"(bf[np * 2 + 1][1])
                             : "r"(addr));
            }
            #pragma unroll
            for (int mt = 0; mt < 4; ++mt)
                #pragma unroll
                for (int nt = 0; nt < 8; ++nt) {
                    asm volatile(
                        "mma.sync.aligned.m16n8k16.row.col.f32.f16.f16.f32 "
                        "{%0,%1,%2,%3}, {%4,%5,%6,%7}, {%8,%9}, {%0,%1,%2,%3};"
                        : "+f"(acc[mt][nt][0]), "+f"(acc[mt][nt][1]),
                          "+f"(acc[mt][nt][2]), "+f"(acc[mt][nt][3])
                        : "r"(af[mt][0]), "r"(af[mt][1]),
                          "r"(af[mt][2]), "r"(af[mt][3]),
                          "r"(bf[nt][0]), "r"(bf[nt][1]));
                }
        }
    }

    #pragma unroll
    for (int mt = 0; mt < 4; ++mt) {
        int r0 = rowBase + wm * 64 + mt * 16 + (lane >> 2);
        #pragma unroll
        for (int nt = 0; nt < 8; ++nt) {
            int col = colBase + wn * 64 + nt * 8 + (lane & 3) * 2;
            float2 sc = *reinterpret_cast<const float2*>(scale + col);
            float2 bi = *reinterpret_cast<const float2*>(bias + col);
            #pragma unroll
            for (int h = 0; h < 2; ++h) {
                int row = r0 + h * 8;
                float ox = fmaxf(acc[mt][nt][h * 2 + 0] * sc.x + bi.x, 0.f);
                float oy = fmaxf(acc[mt][nt][h * 2 + 1] * sc.y + bi.y, 0.f);
                if (MODE == 0) {
                    __half* C = (__half*)Cv;
                    *reinterpret_cast<__half2*>(C + (size_t)row * ldc + col) =
                        __floats2half2_rn(ox, oy);
                } else {
                    float* C = (float*)Cv;
                    float2 rr = *reinterpret_cast<const float2*>(
                        resid + (size_t)row * ldc + col);
                    float2 o = {ox + rr.x, oy + rr.y};
                    *reinterpret_cast<float2*>(C + (size_t)row * ldc + col) = o;
                }
            }
        }
    }
}

// ---------------------------------------------------------------------------
extern "C" void kernel_launch(void* const* d_in, const int* in_sizes, int n_in,
                              void* d_out, int out_size)
{
    const float* i_in   = (const float*)d_in[0];
    const float* s_in   = (const float*)d_in[1];
    const float* pi_in  = (const float*)d_in[2];
    const float* ps_in  = (const float*)d_in[3];
    const int*   mask_s = (const int*)  d_in[4];
    const float* vi = (const float*)d_in[5];
    const float* gi = (const float*)d_in[6];
    const float* bi = (const float*)d_in[7];
    const float* vs = (const float*)d_in[8];
    const float* gs = (const float*)d_in[9];
    const float* bs = (const float*)d_in[10];
    const float* vc = (const float*)d_in[11];
    const float* gc = (const float*)d_in[12];
    const float* bc = (const float*)d_in[13];
    float* out = (float*)d_out;

    float *att_p, *si_p, *ss_p, *sc_p;
    __half *sproj_p, *xcat_p, *i16_p, *s16_p, *vi16_p, *vs16_p, *vc16_p;
    cudaGetSymbolAddress((void**)&att_p,   g_att);
    cudaGetSymbolAddress((void**)&sproj_p, g_sproj);
    cudaGetSymbolAddress((void**)&xcat_p,  g_xcat);
    cudaGetSymbolAddress((void**)&si_p,    g_si);
    cudaGetSymbolAddress((void**)&ss_p,    g_ss);
    cudaGetSymbolAddress((void**)&sc_p,    g_sc);
    cudaGetSymbolAddress((void**)&i16_p,   g_i16);
    cudaGetSymbolAddress((void**)&s16_p,   g_s16);
    cudaGetSymbolAddress((void**)&vi16_p,  g_vi16);
    cudaGetSymbolAddress((void**)&vs16_p,  g_vs16);
    cudaGetSymbolAddress((void**)&vc16_p,  g_vc16);

    cudaFuncSetAttribute(gemm_mma_h<0>,  cudaFuncAttributeMaxDynamicSharedMemorySize, SMEM_DYN);
    cudaFuncSetAttribute(gemm_mma_h2<0>, cudaFuncAttributeMaxDynamicSharedMemorySize, SMEM_DYN2);
    cudaFuncSetAttribute(gemm_mma_h2<1>, cudaFuncAttributeMaxDynamicSharedMemorySize, SMEM_DYN2);

    // launch 0: fp16 conversion of all GEMM operands (fused)
    prep_convert_kernel<<<4096, 256>>>(i_in, i16_p, vi, vi16_p, vc, vc16_p,
                                       s_in, s16_p, vs, vs16_p);

    // launch 1: weight-norm scales (fused)
    rownorm_all_kernel<<<2 * PROJ + OBJ, 256>>>(vi, gi, si_p, vs, gs, ss_p, vc, gc, sc_p);

    // launch 2: attention weights
    att_kernel<<<(B_ * NI + 255) / 256, 256>>>(pi_in, ps_in, mask_s, att_p);

    // launch 3 (profiling slot): i_proj -> xcat[:, 0:1024]   [12800,2048]x[1024,2048]^T
    gemm_mma_h2<0><<<dim3(PROJ / 128, MI / 256), 256, SMEM_DYN2>>>(
        i16_p, vi16_p, si_p, bi, nullptr, xcat_p, OBJ, OBJ, OBJ, 2 * PROJ);

    // launch 4: s_proj = relu_wn(s @ Ws^T): [6400,300]x[1024,300]^T -> half
    gemm_mma_h<0><<<dim3(PROJ / 128, MS / 128), 256, SMEM_DYN>>>(
        s16_p, vs16_p, ss_p, bs, nullptr, sproj_p, SEM, SEMP, SEMP, PROJ);

    // launch 5: i_att -> xcat[:, 1024:2048]: batched [100,50]x[50,1024]
    attmm_kernel<<<dim3(B_, PROJ / 128), 256>>>(att_p, sproj_p, xcat_p);

    // launch 6: out = i + relu_wn(xcat @ Wc^T): [12800,4096]x[2048,4096]^T
    gemm_mma_h2<1><<<dim3(OBJ / 128, MI / 256), 256, SMEM_DYN2>>>(
        xcat_p, vc16_p, sc_p, bc, i_in, out, 2 * PROJ, 2 * PROJ, 2 * PROJ, OBJ);
}

// round 7
// speedup vs baseline: 8.0258x; 1.0300x over previous
#include <cuda_runtime.h>
#include <cuda_fp16.h>
#include <cstdint>
#include <cstddef>

// Problem constants
constexpr int B_   = 128;
constexpr int NI   = 100;
constexpr int NS   = 50;
constexpr int OBJ  = 2048;
constexpr int SEM  = 300;
constexpr int SEMP = 304;   // padded lda for fp16 s/vs (16B-aligned rows)
constexpr int PROJ = 1024;
constexpr int MI = B_ * NI;   // 12800
constexpr int MS = B_ * NS;   // 6400

// 128x128 GEMM pipeline (for the small s_proj GEMM)
constexpr int NST = 3;
constexpr int STAGE_BYTES = 2 * 128 * 128;     // A 16KB + B 16KB
constexpr int SMEM_DYN = NST * STAGE_BYTES;    // 96 KB

// 256x128 GEMM pipeline (big GEMMs)
constexpr int NST2 = 4;
constexpr int STAGE2_BYTES = (256 + 128) * 128;   // A 32KB + B 16KB = 48KB
constexpr int SMEM_DYN2 = NST2 * STAGE2_BYTES;    // 192 KB

// ---------------- scratch (device globals; no runtime allocation) ------------
__device__ __align__(16) float  g_att  [(size_t)B_ * NI * NS];
__device__ __align__(16) __half g_sproj[(size_t)MS * PROJ];
__device__ __align__(16) __half g_xcat [(size_t)MI * 2 * PROJ];
__device__ __align__(16) __half g_i16  [(size_t)MI * OBJ];
__device__ __align__(16) __half g_s16  [(size_t)MS * SEMP];
__device__ __align__(16) __half g_vi16 [(size_t)PROJ * OBJ];
__device__ __align__(16) __half g_vs16 [(size_t)PROJ * SEMP];
__device__ __align__(16) __half g_vc16 [(size_t)OBJ * 2 * PROJ];
__device__ __align__(16) float  g_si[PROJ];
__device__ __align__(16) float  g_ss[PROJ];
__device__ __align__(16) float  g_sc[OBJ];

// ======================= helpers ==============================================
__device__ __forceinline__ uint32_t smem_u32(const void* p) {
    uint32_t a;
    asm("{ .reg .u64 t; cvta.to.shared.u64 t, %1; cvt.u32.u64 %0, t; }"
        : "=r"(a) : "l"(p));
    return a;
}

// ---------------- fused fp16 convert of the 5 GEMM operand buffers ------------
constexpr int CV_NI = MI * OBJ / 4;
constexpr int CV_NVI = PROJ * OBJ / 4;
constexpr int CV_NVC = OBJ * 2 * PROJ / 4;
constexpr int CV_DENSE = CV_NI + CV_NVI + CV_NVC;
constexpr int CV_NS = MS * SEM / 4;
constexpr int CV_NVS = PROJ * SEM / 4;
constexpr int CV_TOT = CV_DENSE + CV_NS + CV_NVS;

__global__ void prep_convert_kernel(const float* __restrict__ i_in, __half* __restrict__ i16,
                                    const float* __restrict__ vi,   __half* __restrict__ vi16,
                                    const float* __restrict__ vc,   __half* __restrict__ vc16,
                                    const float* __restrict__ s,    __half* __restrict__ s16,
                                    const float* __restrict__ vs,   __half* __restrict__ vs16)
{
    for (int t = blockIdx.x * blockDim.x + threadIdx.x; t < CV_TOT;
         t += gridDim.x * blockDim.x) {
        const float* src; __half* dst; int j = t, dj;
        if (j < CV_NI)                      { src = i_in; dst = i16;  dj = j; }
        else if ((j -= CV_NI) < CV_NVI)     { src = vi;   dst = vi16; dj = j; }
        else if ((j -= CV_NVI) < CV_NVC)    { src = vc;   dst = vc16; dj = j; }
        else if ((j -= CV_NVC) < CV_NS) {
            src = s;  dst = s16;
            int row = j / 75, c = j % 75;
            float4 v = reinterpret_cast<const float4*>(src)[j];
            __half2* d = reinterpret_cast<__half2*>(dst + (size_t)row * SEMP + c * 4);
            d[0] = __floats2half2_rn(v.x, v.y);
            d[1] = __floats2half2_rn(v.z, v.w);
            continue;
        } else {
            j -= CV_NS;
            src = vs; dst = vs16;
            int row = j / 75, c = j % 75;
            float4 v = reinterpret_cast<const float4*>(src)[j];
            __half2* d = reinterpret_cast<__half2*>(dst + (size_t)row * SEMP + c * 4);
            d[0] = __floats2half2_rn(v.x, v.y);
            d[1] = __floats2half2_rn(v.z, v.w);
            continue;
        }
        float4 v = reinterpret_cast<const float4*>(src)[dj];
        __half2* d = reinterpret_cast<__half2*>(dst + (size_t)dj * 4);
        d[0] = __floats2half2_rn(v.x, v.y);
        d[1] = __floats2half2_rn(v.z, v.w);
    }
}

// ---------------- fused row-norm scales ---------------------------------------
__global__ void rownorm_all_kernel(const float* __restrict__ vi, const float* __restrict__ gi,
                                   float* __restrict__ si,
                                   const float* __restrict__ vs, const float* __restrict__ gs,
                                   float* __restrict__ ss,
                                   const float* __restrict__ vc, const float* __restrict__ gc,
                                   float* __restrict__ sc)
{
    int blk = blockIdx.x;
    const float *v, *g; float* out; int K, r;
    if (blk < PROJ)            { v = vi; g = gi; out = si; K = OBJ;      r = blk; }
    else if (blk < 2 * PROJ)   { v = vs; g = gs; out = ss; K = SEM;      r = blk - PROJ; }
    else                       { v = vc; g = gc; out = sc; K = 2 * PROJ; r = blk - 2 * PROJ; }

    float s = 0.f;
    for (int k = threadIdx.x; k < K; k += blockDim.x) {
        float x = v[(size_t)r * K + k];
        s += x * x;
    }
    __shared__ float red[256];
    red[threadIdx.x] = s;
    __syncthreads();
    #pragma unroll
    for (int o = 128; o > 0; o >>= 1) {
        if (threadIdx.x < o) red[threadIdx.x] += red[threadIdx.x + o];
        __syncthreads();
    }
    if (threadIdx.x == 0) out[r] = g[r] * rsqrtf(red[0]);
}

// ---------------- attention softmax -------------------------------------------
__global__ void att_kernel(const float* __restrict__ pi, const float* __restrict__ ps,
                           const int* __restrict__ mask_s, float* __restrict__ att)
{
    int idx = blockIdx.x * blockDim.x + threadIdx.x;
    if (idx >= B_ * NI) return;
    int b = idx / NI;
    float px = pi[idx * 2 + 0];
    float py = pi[idx * 2 + 1];
    int m = mask_s[b];
    const float* psb = ps + (size_t)b * NS * 2;

    float d[NS];
    float mx = -1e30f;
    #pragma unroll
    for (int j = 0; j < NS; j++) {
        float dx = px - psb[2 * j + 0];
        float dy = py - psb[2 * j + 1];
        d[j] = sqrtf(dx * dx + dy * dy);
        if (j < m) mx = fmaxf(mx, d[j]);
    }
    float sum = 0.f;
    #pragma unroll
    for (int j = 0; j < NS; j++) {
        float e = (j < m) ? __expf(d[j] - mx) : 0.f;
        d[j] = e;
        sum += e;
    }
    float inv = 1.f / sum;
    #pragma unroll
    for (int j = 0; j < NS; j++) att[(size_t)idx * NS + j] = d[j] * inv;
}

// ---------------- batched small matmul: i_att = att @ s_proj ------------------
__global__ __launch_bounds__(256) void attmm_kernel(const float* __restrict__ att,
                                                    const __half* __restrict__ sproj,
                                                    __half* __restrict__ xcat)
{
    __shared__ float at[NI][NS];
    __shared__ float sp[NS][128];
    int b = blockIdx.x;
    int ncol = blockIdx.y * 128;
    int tid = threadIdx.x;

    for (int e = tid; e < NI * NS; e += 256)
        at[e / NS][e % NS] = att[(size_t)b * NI * NS + e];
    for (int e = tid; e < NS * 128; e += 256) {
        int k = e >> 7, n = e & 127;
        sp[k][n] = __half2float(sproj[((size_t)b * NS + k) * PROJ + ncol + n]);
    }
    __syncthreads();

    int n = tid & 127;
    int mg = tid >> 7;
    for (int m = mg * 50; m < mg * 50 + 50; m++) {
        float acc = 0.f;
        #pragma unroll
        for (int k = 0; k < NS; k++) acc = fmaf(at[m][k], sp[k][n], acc);
        xcat[((size_t)b * NI + m) * (2 * PROJ) + PROJ + ncol + n] = __float2half_rn(acc);
    }
}

// ================ fp16 GEMM 128x128 (used for s_proj; handles K tails) ========
template<int MODE>
__global__ __launch_bounds__(256, 2) void gemm_mma_h(
    const __half* __restrict__ A, const __half* __restrict__ Bm,
    const float* __restrict__ scale, const float* __restrict__ bias,
    const float* __restrict__ resid, void* __restrict__ Cv,
    int K, int lda, int ldb, int ldc)
{
    extern __shared__ __align__(128) char dynsmem[];
    const uint32_t sbase = smem_u32(dynsmem);
    const int tid  = threadIdx.x;
    const int lane = tid & 31;
    const int wid  = tid >> 5;
    const int wm   = wid >> 2;
    const int wn   = wid & 3;
    const int rowBase = blockIdx.y * 128;
    const int colBase = blockIdx.x * 128;

    const __half* Ablk = A  + (size_t)rowBase * lda;
    const __half* Bblk = Bm + (size_t)colBase * ldb;
    const int KT = (K + 63) / 64;

    auto load_chunk = [&](int L) {
        const int s = L % NST;
        const int k0 = L * 64;
        const uint32_t stage = sbase + s * STAGE_BYTES;
        const bool tail = (k0 + 64 > K);
        #pragma unroll
        for (int it = 0; it < 8; ++it) {
            int t = tid + it * 256;
            int which = t >> 10;
            int r = (t >> 3) & 127;
            int j = t & 7;
            int gk = k0 + j * 8;
            const __half* src = (which ? Bblk + (size_t)r * ldb
                                       : Ablk + (size_t)r * lda) + gk;
            uint32_t dst = stage + which * 16384 + r * 128 + ((j ^ (r & 7)) << 4);
            if (!tail) {
                asm volatile("cp.async.cg.shared.global [%0], [%1], 16;"
                             :: "r"(dst), "l"(src) : "memory");
            } else {
                uint32_t w[4];
                #pragma unroll
                for (int u = 0; u < 4; ++u) {
                    __half lo = (gk + 2 * u     < K) ? src[2 * u]     : __half(0.f);
                    __half hi = (gk + 2 * u + 1 < K) ? src[2 * u + 1] : __half(0.f);
                    __half2 h2 = __halves2half2(lo, hi);
                    w[u] = *reinterpret_cast<uint32_t*>(&h2);
                }
                asm volatile("st.shared.v4.b32 [%0], {%1,%2,%3,%4};"
                             :: "r"(dst), "r"(w[0]), "r"(w[1]), "r"(w[2]), "r"(w[3])
                             : "memory");
            }
        }
    };

    #pragma unroll
    for (int p = 0; p < NST - 1; ++p) {
        if (p < KT) load_chunk(p);
        asm volatile("cp.async.commit_group;" ::: "memory");
    }

    float acc[4][4][4];
    #pragma unroll
    for (int a = 0; a < 4; a++)
        #pragma unroll
        for (int b = 0; b < 4; b++)
            #pragma unroll
            for (int c = 0; c < 4; c++) acc[a][b][c] = 0.f;

    for (int c = 0; c < KT; ++c) {
        asm volatile("cp.async.wait_group 1;" ::: "memory");
        __syncthreads();

        const int L = c + NST - 1;
        if (L < KT) load_chunk(L);
        asm volatile("cp.async.commit_group;" ::: "memory");

        const uint32_t ast = sbase + (c % NST) * STAGE_BYTES;
        const uint32_t bst = ast + 16384;

        #pragma unroll
        for (int ks = 0; ks < 4; ++ks) {
            uint32_t af[4][4], bf[4][2];
            #pragma unroll
            for (int mt = 0; mt < 4; ++mt) {
                int r = wm * 64 + mt * 16 + (lane & 15);
                int ch = ks * 2 + (lane >> 4);
                uint32_t addr = ast + r * 128 + ((ch ^ (r & 7)) << 4);
                asm volatile("ldmatrix.sync.aligned.m8n8.x4.shared.b16 "
                             "{%0,%1,%2,%3}, [%4];"
                             : "=r"(af[mt][0]), "=r"(af[mt][1]),
                               "=r"(af[mt][2]), "=r"(af[mt][3])
                             : "r"(addr));
            }
            #pragma unroll
            for (int np = 0; np < 2; ++np) {
                int tile = np * 2 + (lane >> 4);
                int half_k = (lane >> 3) & 1;
                int r = wn * 32 + tile * 8 + (lane & 7);
                int ch = ks * 2 + half_k;
                uint32_t addr = bst + r * 128 + ((ch ^ (r & 7)) << 4);
                asm volatile("ldmatrix.sync.aligned.m8n8.x4.shared.b16 "
                             "{%0,%1,%2,%3}, [%4];"
                             : "=r"(bf[np * 2][0]), "=r"(bf[np * 2][1]),
                               "=r"(bf[np * 2 + 1][0]), "=r"(bf[np * 2 + 1][1])
                             : "r"(addr));
            }
            #pragma unroll
            for (int mt = 0; mt < 4; ++mt)
                #pragma unroll
                for (int nt = 0; nt < 4; ++nt) {
                    asm volatile(
                        "mma.sync.aligned.m16n8k16.row.col.f32.f16.f16.f32 "
                        "{%0,%1,%2,%3}, {%4,%5,%6,%7}, {%8,%9}, {%0,%1,%2,%3};"
                        : "+f"(acc[mt][nt][0]), "+f"(acc[mt][nt][1]),
                          "+f"(acc[mt][nt][2]), "+f"(acc[mt][nt][3])
                        : "r"(af[mt][0]), "r"(af[mt][1]),
                          "r"(af[mt][2]), "r"(af[mt][3]),
                          "r"(bf[nt][0]), "r"(bf[nt][1]));
                }
        }
    }

    #pragma unroll
    for (int mt = 0; mt < 4; ++mt) {
        int r0 = rowBase + wm * 64 + mt * 16 + (lane >> 2);
        #pragma unroll
        for (int nt = 0; nt < 4; ++nt) {
            int col = colBase + wn * 32 + nt * 8 + (lane & 3) * 2;
            float2 sc = *reinterpret_cast<const float2*>(scale + col);
            float2 bi = *reinterpret_cast<const float2*>(bias + col);
            #pragma unroll
            for (int h = 0; h < 2; ++h) {
                int row = r0 + h * 8;
                float ox = fmaxf(acc[mt][nt][h * 2 + 0] * sc.x + bi.x, 0.f);
                float oy = fmaxf(acc[mt][nt][h * 2 + 1] * sc.y + bi.y, 0.f);
                if (MODE == 0) {
                    __half* C = (__half*)Cv;
                    *reinterpret_cast<__half2*>(C + (size_t)row * ldc + col) =
                        __floats2half2_rn(ox, oy);
                } else {
                    float* C = (float*)Cv;
                    float2 rr = *reinterpret_cast<const float2*>(
                        resid + (size_t)row * ldc + col);
                    float2 o = {ox + rr.x, oy + rr.y};
                    *reinterpret_cast<float2*>(C + (size_t)row * ldc + col) = o;
                }
            }
        }
    }
}

// ================ fp16 GEMM 256x128, 4-stage, frag-double-buffered =============
// 8 warps in 4x2 grid, warp tile 64x64. K % 64 == 0.
// MODE 0: C(half) = relu(acc*scale+bias)   MODE 1: C(float) = resid + relu(...)
template<int MODE>
__global__ __launch_bounds__(256, 1) void gemm_mma_h2(
    const __half* __restrict__ A, const __half* __restrict__ Bm,
    const float* __restrict__ scale, const float* __restrict__ bias,
    const float* __restrict__ resid, void* __restrict__ Cv,
    int K, int lda, int ldb, int ldc)
{
    extern __shared__ __align__(128) char dynsmem[];
    const uint32_t sbase = smem_u32(dynsmem);
    const int tid  = threadIdx.x;
    const int lane = tid & 31;
    const int wid  = tid >> 5;
    const int wm   = wid >> 1;   // 0..3
    const int wn   = wid & 1;    // 0..1
    const int rowBase = blockIdx.y * 256;
    const int colBase = blockIdx.x * 128;

    const __half* Ablk = A  + (size_t)rowBase * lda;
    const __half* Bblk = Bm + (size_t)colBase * ldb;
    const int KT = K / 64;

    // precomputed ldmatrix base offsets (swizzled row part)
    const int rA = wm * 64 + (lane & 15);          // + mt*16
    const int rB = wn * 64 + (lane & 7);           // + tile*8
    const int chA_half = (lane >> 4);              // 0/1
    const int tB_base  = (lane >> 4);              // 0/1
    const int chB_half = (lane >> 3) & 1;

    auto load_chunk = [&](int L) {
        const int s = L % NST2;
        const int k0 = L * 64;
        const uint32_t stage = sbase + s * STAGE2_BYTES;
        #pragma unroll
        for (int it = 0; it < 12; ++it) {
            int t = tid + it * 256;            // 0..3071
            bool isB = t >= 2048;
            int tt = isB ? t - 2048 : t;
            int r = tt >> 3;
            int j = tt & 7;
            int gk = k0 + j * 8;
            const __half* src = (isB ? Bblk + (size_t)r * ldb
                                     : Ablk + (size_t)r * lda) + gk;
            uint32_t dst = stage + (isB ? 32768 : 0) + r * 128 + ((j ^ (r & 7)) << 4);
            asm volatile("cp.async.cg.shared.global [%0], [%1], 16;"
                         :: "r"(dst), "l"(src) : "memory");
        }
    };

    #pragma unroll
    for (int p = 0; p < NST2 - 1; ++p) {
        if (p < KT) load_chunk(p);
        asm volatile("cp.async.commit_group;" ::: "memory");
    }

    float acc[4][8][4];
    #pragma unroll
    for (int a = 0; a < 4; a++)
        #pragma unroll
        for (int b = 0; b < 8; b++)
            #pragma unroll
            for (int c = 0; c < 4; c++) acc[a][b][c] = 0.f;

    uint32_t af[2][4][4], bf[2][8][2];

    // fragment loader for k16-step ks of the chunk at (ast, bst) into buffer pb
    auto load_frags = [&](uint32_t ast, uint32_t bst, int ks, int pb) {
        #pragma unroll
        for (int mt = 0; mt < 4; ++mt) {
            int r = rA + mt * 16;
            int ch = ks * 2 + chA_half;
            uint32_t addr = ast + r * 128 + ((ch ^ (r & 7)) << 4);
            asm volatile("ldmatrix.sync.aligned.m8n8.x4.shared.b16 "
                         "{%0,%1,%2,%3}, [%4];"
                         : "=r"(af[pb][mt][0]), "=r"(af[pb][mt][1]),
                           "=r"(af[pb][mt][2]), "=r"(af[pb][mt][3])
                         : "r"(addr));
        }
        #pragma unroll
        for (int np = 0; np < 4; ++np) {
            int tile = np * 2 + tB_base;
            int r = rB + tile * 8;
            int ch = ks * 2 + chB_half;
            uint32_t addr = bst + r * 128 + ((ch ^ (r & 7)) << 4);
            asm volatile("ldmatrix.sync.aligned.m8n8.x4.shared.b16 "
                         "{%0,%1,%2,%3}, [%4];"
                         : "=r"(bf[pb][np * 2][0]), "=r"(bf[pb][np * 2][1]),
                           "=r"(bf[pb][np * 2 + 1][0]), "=r"(bf[pb][np * 2 + 1][1])
                         : "r"(addr));
        }
    };

    for (int c = 0; c < KT; ++c) {
        asm volatile("cp.async.wait_group %0;" :: "n"(NST2 - 2) : "memory");
        __syncthreads();

        const int L = c + NST2 - 1;
        if (L < KT) load_chunk(L);
        asm volatile("cp.async.commit_group;" ::: "memory");

        const uint32_t ast = sbase + (c % NST2) * STAGE2_BYTES;
        const uint32_t bst = ast + 32768;

        load_frags(ast, bst, 0, 0);
        #pragma unroll
        for (int ks = 0; ks < 4; ++ks) {
            if (ks < 3) load_frags(ast, bst, ks + 1, (ks + 1) & 1);
            const int pb = ks & 1;
            #pragma unroll
            for (int mt = 0; mt < 4; ++mt)
                #pragma unroll
                for (int nt = 0; nt < 8; ++nt) {
                    asm volatile(
                        "mma.sync.aligned.m16n8k16.row.col.f32.f16.f16.f32 "
                        "{%0,%1,%2,%3}, {%4,%5,%6,%7}, {%8,%9}, {%0,%1,%2,%3};"
                        : "+f"(acc[mt][nt][0]), "+f"(acc[mt][nt][1]),
                          "+f"(acc[mt][nt][2]), "+f"(acc[mt][nt][3])
                        : "r"(af[pb][mt][0]), "r"(af[pb][mt][1]),
                          "r"(af[pb][mt][2]), "r"(af[pb][mt][3]),
                          "r"(bf[pb][nt][0]), "r"(bf[pb][nt][1]));
                }
        }
    }

    #pragma unroll
    for (int mt = 0; mt < 4; ++mt) {
        int r0 = rowBase + wm * 64 + mt * 16 + (lane >> 2);
        #pragma unroll
        for (int nt = 0; nt < 8; ++nt) {
            int col = colBase + wn * 64 + nt * 8 + (lane & 3) * 2;
            float2 sc = *reinterpret_cast<const float2*>(scale + col);
            float2 bi = *reinterpret_cast<const float2*>(bias + col);
            #pragma unroll
            for (int h = 0; h < 2; ++h) {
                int row = r0 + h * 8;
                float ox = fmaxf(acc[mt][nt][h * 2 + 0] * sc.x + bi.x, 0.f);
                float oy = fmaxf(acc[mt][nt][h * 2 + 1] * sc.y + bi.y, 0.f);
                if (MODE == 0) {
                    __half* C = (__half*)Cv;
                    *reinterpret_cast<__half2*>(C + (size_t)row * ldc + col) =
                        __floats2half2_rn(ox, oy);
                } else {
                    float* C = (float*)Cv;
                    float2 rr = *reinterpret_cast<const float2*>(
                        resid + (size_t)row * ldc + col);
                    float2 o = {ox + rr.x, oy + rr.y};
                    *reinterpret_cast<float2*>(C + (size_t)row * ldc + col) = o;
                }
            }
        }
    }
}

// ---------------------------------------------------------------------------
extern "C" void kernel_launch(void* const* d_in, const int* in_sizes, int n_in,
                              void* d_out, int out_size)
{
    const float* i_in   = (const float*)d_in[0];
    const float* s_in   = (const float*)d_in[1];
    const float* pi_in  = (const float*)d_in[2];
    const float* ps_in  = (const float*)d_in[3];
    const int*   mask_s = (const int*)  d_in[4];
    const float* vi = (const float*)d_in[5];
    const float* gi = (const float*)d_in[6];
    const float* bi = (const float*)d_in[7];
    const float* vs = (const float*)d_in[8];
    const float* gs = (const float*)d_in[9];
    const float* bs = (const float*)d_in[10];
    const float* vc = (const float*)d_in[11];
    const float* gc = (const float*)d_in[12];
    const float* bc = (const float*)d_in[13];
    float* out = (float*)d_out;

    float *att_p, *si_p, *ss_p, *sc_p;
    __half *sproj_p, *xcat_p, *i16_p, *s16_p, *vi16_p, *vs16_p, *vc16_p;
    cudaGetSymbolAddress((void**)&att_p,   g_att);
    cudaGetSymbolAddress((void**)&sproj_p, g_sproj);
    cudaGetSymbolAddress((void**)&xcat_p,  g_xcat);
    cudaGetSymbolAddress((void**)&si_p,    g_si);
    cudaGetSymbolAddress((void**)&ss_p,    g_ss);
    cudaGetSymbolAddress((void**)&sc_p,    g_sc);
    cudaGetSymbolAddress((void**)&i16_p,   g_i16);
    cudaGetSymbolAddress((void**)&s16_p,   g_s16);
    cudaGetSymbolAddress((void**)&vi16_p,  g_vi16);
    cudaGetSymbolAddress((void**)&vs16_p,  g_vs16);
    cudaGetSymbolAddress((void**)&vc16_p,  g_vc16);

    cudaFuncSetAttribute(gemm_mma_h<0>,  cudaFuncAttributeMaxDynamicSharedMemorySize, SMEM_DYN);
    cudaFuncSetAttribute(gemm_mma_h2<0>, cudaFuncAttributeMaxDynamicSharedMemorySize, SMEM_DYN2);
    cudaFuncSetAttribute(gemm_mma_h2<1>, cudaFuncAttributeMaxDynamicSharedMemorySize, SMEM_DYN2);

    // launch 0: fp16 conversion of all GEMM operands (fused)
    prep_convert_kernel<<<4096, 256>>>(i_in, i16_p, vi, vi16_p, vc, vc16_p,
                                       s_in, s16_p, vs, vs16_p);

    // launch 1: weight-norm scales (fused)
    rownorm_all_kernel<<<2 * PROJ + OBJ, 256>>>(vi, gi, si_p, vs, gs, ss_p, vc, gc, sc_p);

    // launch 2: attention weights
    att_kernel<<<(B_ * NI + 255) / 256, 256>>>(pi_in, ps_in, mask_s, att_p);

    // launch 3 (profiling slot): i_proj -> xcat[:, 0:1024]   [12800,2048]x[1024,2048]^T
    gemm_mma_h2<0><<<dim3(PROJ / 128, MI / 256), 256, SMEM_DYN2>>>(
        i16_p, vi16_p, si_p, bi, nullptr, xcat_p, OBJ, OBJ, OBJ, 2 * PROJ);

    // launch 4: s_proj = relu_wn(s @ Ws^T): [6400,300]x[1024,300]^T -> half
    gemm_mma_h<0><<<dim3(PROJ / 128, MS / 128), 256, SMEM_DYN>>>(
        s16_p, vs16_p, ss_p, bs, nullptr, sproj_p, SEM, SEMP, SEMP, PROJ);

    // launch 5: i_att -> xcat[:, 1024:2048]: batched [100,50]x[50,1024]
    attmm_kernel<<<dim3(B_, PROJ / 128), 256>>>(att_p, sproj_p, xcat_p);

    // launch 6: out = i + relu_wn(xcat @ Wc^T): [12800,4096]x[2048,4096]^T
    gemm_mma_h2<1><<<dim3(OBJ / 128, MI / 256), 256, SMEM_DYN2>>>(
        xcat_p, vc16_p, sc_p, bc, i_in, out, 2 * PROJ, 2 * PROJ, 2 * PROJ, OBJ);
}

// round 8
// speedup vs baseline: 8.5081x; 1.0601x over previous
#include <cuda_runtime.h>
#include <cuda_fp16.h>
#include <cstdint>
#include <cstddef>

// Problem constants
constexpr int B_   = 128;
constexpr int NI   = 100;
constexpr int NS   = 50;
constexpr int OBJ  = 2048;
constexpr int SEM  = 300;
constexpr int SEMP = 304;   // padded lda for fp16 s/vs (16B-aligned rows)
constexpr int PROJ = 1024;
constexpr int MI = B_ * NI;   // 12800
constexpr int MS = B_ * NS;   // 6400

// 128x128 GEMM pipeline (for the small s_proj GEMM)
constexpr int NST = 3;
constexpr int STAGE_BYTES = 2 * 128 * 128;     // A 16KB + B 16KB
constexpr int SMEM_DYN = NST * STAGE_BYTES;    // 96 KB

// 256x128 GEMM pipeline (big GEMMs)
constexpr int NST2 = 4;
constexpr int STAGE2_BYTES = (256 + 128) * 128;   // A 32KB + B 16KB = 48KB
constexpr int SMEM_DYN2 = NST2 * STAGE2_BYTES;    // 192 KB

// ---------------- scratch (device globals; no runtime allocation) ------------
__device__ __align__(16) float  g_att  [(size_t)B_ * NI * NS];
__device__ __align__(16) __half g_sproj[(size_t)MS * PROJ];
__device__ __align__(16) __half g_xcat [(size_t)MI * 2 * PROJ];
__device__ __align__(16) __half g_i16  [(size_t)MI * OBJ];
__device__ __align__(16) __half g_s16  [(size_t)MS * SEMP];
__device__ __align__(16) __half g_vi16 [(size_t)PROJ * OBJ];
__device__ __align__(16) __half g_vs16 [(size_t)PROJ * SEMP];
__device__ __align__(16) __half g_vc16 [(size_t)OBJ * 2 * PROJ];
__device__ __align__(16) float  g_si[PROJ];
__device__ __align__(16) float  g_ss[PROJ];
__device__ __align__(16) float  g_sc[OBJ];

// ======================= helpers ==============================================
__device__ __forceinline__ uint32_t smem_u32(const void* p) {
    uint32_t a;
    asm("{ .reg .u64 t; cvta.to.shared.u64 t, %1; cvt.u32.u64 %0, t; }"
        : "=r"(a) : "l"(p));
    return a;
}

// ---------------- fused fp16 convert of the 5 GEMM operand buffers ------------
constexpr int CV_NI = MI * OBJ / 4;
constexpr int CV_NVI = PROJ * OBJ / 4;
constexpr int CV_NVC = OBJ * 2 * PROJ / 4;
constexpr int CV_DENSE = CV_NI + CV_NVI + CV_NVC;
constexpr int CV_NS = MS * SEM / 4;
constexpr int CV_NVS = PROJ * SEM / 4;
constexpr int CV_TOT = CV_DENSE + CV_NS + CV_NVS;

__global__ void prep_convert_kernel(const float* __restrict__ i_in, __half* __restrict__ i16,
                                    const float* __restrict__ vi,   __half* __restrict__ vi16,
                                    const float* __restrict__ vc,   __half* __restrict__ vc16,
                                    const float* __restrict__ s,    __half* __restrict__ s16,
                                    const float* __restrict__ vs,   __half* __restrict__ vs16)
{
    for (int t = blockIdx.x * blockDim.x + threadIdx.x; t < CV_TOT;
         t += gridDim.x * blockDim.x) {
        const float* src; __half* dst; int j = t, dj;
        if (j < CV_NI)                      { src = i_in; dst = i16;  dj = j; }
        else if ((j -= CV_NI) < CV_NVI)     { src = vi;   dst = vi16; dj = j; }
        else if ((j -= CV_NVI) < CV_NVC)    { src = vc;   dst = vc16; dj = j; }
        else if ((j -= CV_NVC) < CV_NS) {
            src = s;  dst = s16;
            int row = j / 75, c = j % 75;
            float4 v = reinterpret_cast<const float4*>(src)[j];
            __half2* d = reinterpret_cast<__half2*>(dst + (size_t)row * SEMP + c * 4);
            d[0] = __floats2half2_rn(v.x, v.y);
            d[1] = __floats2half2_rn(v.z, v.w);
            continue;
        } else {
            j -= CV_NS;
            src = vs; dst = vs16;
            int row = j / 75, c = j % 75;
            float4 v = reinterpret_cast<const float4*>(src)[j];
            __half2* d = reinterpret_cast<__half2*>(dst + (size_t)row * SEMP + c * 4);
            d[0] = __floats2half2_rn(v.x, v.y);
            d[1] = __floats2half2_rn(v.z, v.w);
            continue;
        }
        float4 v = reinterpret_cast<const float4*>(src)[dj];
        __half2* d = reinterpret_cast<__half2*>(dst + (size_t)dj * 4);
        d[0] = __floats2half2_rn(v.x, v.y);
        d[1] = __floats2half2_rn(v.z, v.w);
    }
}

// ------------- fused row-norm scales + attention softmax ----------------------
// blocks [0, 2*PROJ+OBJ): rownorm rows.  blocks [2*PROJ+OBJ, +50): att softmax.
constexpr int RN_BLOCKS = 2 * PROJ + OBJ;
constexpr int ATT_BLOCKS = (B_ * NI + 255) / 256;

__global__ void prep2_kernel(const float* __restrict__ vi, const float* __restrict__ gi,
                             float* __restrict__ si,
                             const float* __restrict__ vs, const float* __restrict__ gs,
                             float* __restrict__ ss,
                             const float* __restrict__ vc, const float* __restrict__ gc,
                             float* __restrict__ sc,
                             const float* __restrict__ pi, const float* __restrict__ ps,
                             const int* __restrict__ mask_s, float* __restrict__ att)
{
    int blk = blockIdx.x;
    if (blk >= RN_BLOCKS) {
        // ---- attention softmax ----
        int idx = (blk - RN_BLOCKS) * blockDim.x + threadIdx.x;
        if (idx >= B_ * NI) return;
        int b = idx / NI;
        float px = pi[idx * 2 + 0];
        float py = pi[idx * 2 + 1];
        int m = mask_s[b];
        const float* psb = ps + (size_t)b * NS * 2;

        float d[NS];
        float mx = -1e30f;
        #pragma unroll
        for (int j = 0; j < NS; j++) {
            float dx = px - psb[2 * j + 0];
            float dy = py - psb[2 * j + 1];
            d[j] = sqrtf(dx * dx + dy * dy);
            if (j < m) mx = fmaxf(mx, d[j]);
        }
        float sum = 0.f;
        #pragma unroll
        for (int j = 0; j < NS; j++) {
            float e = (j < m) ? __expf(d[j] - mx) : 0.f;
            d[j] = e;
            sum += e;
        }
        float inv = 1.f / sum;
        #pragma unroll
        for (int j = 0; j < NS; j++) att[(size_t)idx * NS + j] = d[j] * inv;
        return;
    }
    // ---- rownorm ----
    const float *v, *g; float* out; int K, r;
    if (blk < PROJ)            { v = vi; g = gi; out = si; K = OBJ;      r = blk; }
    else if (blk < 2 * PROJ)   { v = vs; g = gs; out = ss; K = SEM;      r = blk - PROJ; }
    else                       { v = vc; g = gc; out = sc; K = 2 * PROJ; r = blk - 2 * PROJ; }

    float s = 0.f;
    for (int k = threadIdx.x; k < K; k += blockDim.x) {
        float x = v[(size_t)r * K + k];
        s += x * x;
    }
    __shared__ float red[256];
    red[threadIdx.x] = s;
    __syncthreads();
    #pragma unroll
    for (int o = 128; o > 0; o >>= 1) {
        if (threadIdx.x < o) red[threadIdx.x] += red[threadIdx.x + o];
        __syncthreads();
    }
    if (threadIdx.x == 0) out[r] = g[r] * rsqrtf(red[0]);
}

// ---------------- batched small matmul: i_att = att @ s_proj ------------------
__global__ __launch_bounds__(256) void attmm_kernel(const float* __restrict__ att,
                                                    const __half* __restrict__ sproj,
                                                    __half* __restrict__ xcat)
{
    __shared__ float at[NI][NS];
    __shared__ float sp[NS][128];
    int b = blockIdx.x;
    int ncol = blockIdx.y * 128;
    int tid = threadIdx.x;

    for (int e = tid; e < NI * NS; e += 256)
        at[e / NS][e % NS] = att[(size_t)b * NI * NS + e];
    for (int e = tid; e < NS * 128; e += 256) {
        int k = e >> 7, n = e & 127;
        sp[k][n] = __half2float(sproj[((size_t)b * NS + k) * PROJ + ncol + n]);
    }
    __syncthreads();

    int n = tid & 127;
    int mg = tid >> 7;
    for (int m = mg * 50; m < mg * 50 + 50; m++) {
        float acc = 0.f;
        #pragma unroll
        for (int k = 0; k < NS; k++) acc = fmaf(at[m][k], sp[k][n], acc);
        xcat[((size_t)b * NI + m) * (2 * PROJ) + PROJ + ncol + n] = __float2half_rn(acc);
    }
}

// ================ fp16 GEMM 128x128 (used for s_proj; handles K tails) ========
template<int MODE>
__global__ __launch_bounds__(256, 2) void gemm_mma_h(
    const __half* __restrict__ A, const __half* __restrict__ Bm,
    const float* __restrict__ scale, const float* __restrict__ bias,
    const float* __restrict__ resid, void* __restrict__ Cv,
    int K, int lda, int ldb, int ldc)
{
    extern __shared__ __align__(128) char dynsmem[];
    const uint32_t sbase = smem_u32(dynsmem);
    const int tid  = threadIdx.x;
    const int lane = tid & 31;
    const int wid  = tid >> 5;
    const int wm   = wid >> 2;
    const int wn   = wid & 3;
    const int rowBase = blockIdx.y * 128;
    const int colBase = blockIdx.x * 128;

    const __half* Ablk = A  + (size_t)rowBase * lda;
    const __half* Bblk = Bm + (size_t)colBase * ldb;
    const int KT = (K + 63) / 64;

    auto load_chunk = [&](int L) {
        const int s = L % NST;
        const int k0 = L * 64;
        const uint32_t stage = sbase + s * STAGE_BYTES;
        const bool tail = (k0 + 64 > K);
        #pragma unroll
        for (int it = 0; it < 8; ++it) {
            int t = tid + it * 256;
            int which = t >> 10;
            int r = (t >> 3) & 127;
            int j = t & 7;
            int gk = k0 + j * 8;
            const __half* src = (which ? Bblk + (size_t)r * ldb
                                       : Ablk + (size_t)r * lda) + gk;
            uint32_t dst = stage + which * 16384 + r * 128 + ((j ^ (r & 7)) << 4);
            if (!tail) {
                asm volatile("cp.async.cg.shared.global [%0], [%1], 16;"
                             :: "r"(dst), "l"(src) : "memory");
            } else {
                uint32_t w[4];
                #pragma unroll
                for (int u = 0; u < 4; ++u) {
                    __half lo = (gk + 2 * u     < K) ? src[2 * u]     : __half(0.f);
                    __half hi = (gk + 2 * u + 1 < K) ? src[2 * u + 1] : __half(0.f);
                    __half2 h2 = __halves2half2(lo, hi);
                    w[u] = *reinterpret_cast<uint32_t*>(&h2);
                }
                asm volatile("st.shared.v4.b32 [%0], {%1,%2,%3,%4};"
                             :: "r"(dst), "r"(w[0]), "r"(w[1]), "r"(w[2]), "r"(w[3])
                             : "memory");
            }
        }
    };

    #pragma unroll
    for (int p = 0; p < NST - 1; ++p) {
        if (p < KT) load_chunk(p);
        asm volatile("cp.async.commit_group;" ::: "memory");
    }

    float acc[4][4][4];
    #pragma unroll
    for (int a = 0; a < 4; a++)
        #pragma unroll
        for (int b = 0; b < 4; b++)
            #pragma unroll
            for (int c = 0; c < 4; c++) acc[a][b][c] = 0.f;

    for (int c = 0; c < KT; ++c) {
        asm volatile("cp.async.wait_group 1;" ::: "memory");
        __syncthreads();

        const int L = c + NST - 1;
        if (L < KT) load_chunk(L);
        asm volatile("cp.async.commit_group;" ::: "memory");

        const uint32_t ast = sbase + (c % NST) * STAGE_BYTES;
        const uint32_t bst = ast + 16384;

        #pragma unroll
        for (int ks = 0; ks < 4; ++ks) {
            uint32_t af[4][4], bf[4][2];
            #pragma unroll
            for (int mt = 0; mt < 4; ++mt) {
                int r = wm * 64 + mt * 16 + (lane & 15);
                int ch = ks * 2 + (lane >> 4);
                uint32_t addr = ast + r * 128 + ((ch ^ (r & 7)) << 4);
                asm volatile("ldmatrix.sync.aligned.m8n8.x4.shared.b16 "
                             "{%0,%1,%2,%3}, [%4];"
                             : "=r"(af[mt][0]), "=r"(af[mt][1]),
                               "=r"(af[mt][2]), "=r"(af[mt][3])
                             : "r"(addr));
            }
            #pragma unroll
            for (int np = 0; np < 2; ++np) {
                int tile = np * 2 + (lane >> 4);
                int half_k = (lane >> 3) & 1;
                int r = wn * 32 + tile * 8 + (lane & 7);
                int ch = ks * 2 + half_k;
                uint32_t addr = bst + r * 128 + ((ch ^ (r & 7)) << 4);
                asm volatile("ldmatrix.sync.aligned.m8n8.x4.shared.b16 "
                             "{%0,%1,%2,%3}, [%4];"
                             : "=r"(bf[np * 2][0]), "=r"(bf[np * 2][1]),
                               "=r"(bf[np * 2 + 1][0]), "=r"(bf[np * 2 + 1][1])
                             : "r"(addr));
            }
            #pragma unroll
            for (int mt = 0; mt < 4; ++mt)
                #pragma unroll
                for (int nt = 0; nt < 4; ++nt) {
                    asm volatile(
                        "mma.sync.aligned.m16n8k16.row.col.f32.f16.f16.f32 "
                        "{%0,%1,%2,%3}, {%4,%5,%6,%7}, {%8,%9}, {%0,%1,%2,%3};"
                        : "+f"(acc[mt][nt][0]), "+f"(acc[mt][nt][1]),
                          "+f"(acc[mt][nt][2]), "+f"(acc[mt][nt][3])
                        : "r"(af[mt][0]), "r"(af[mt][1]),
                          "r"(af[mt][2]), "r"(af[mt][3]),
                          "r"(bf[nt][0]), "r"(bf[nt][1]));
                }
        }
    }

    #pragma unroll
    for (int mt = 0; mt < 4; ++mt) {
        int r0 = rowBase + wm * 64 + mt * 16 + (lane >> 2);
        #pragma unroll
        for (int nt = 0; nt < 4; ++nt) {
            int col = colBase + wn * 32 + nt * 8 + (lane & 3) * 2;
            float2 sc = *reinterpret_cast<const float2*>(scale + col);
            float2 bi = *reinterpret_cast<const float2*>(bias + col);
            #pragma unroll
            for (int h = 0; h < 2; ++h) {
                int row = r0 + h * 8;
                float ox = fmaxf(acc[mt][nt][h * 2 + 0] * sc.x + bi.x, 0.f);
                float oy = fmaxf(acc[mt][nt][h * 2 + 1] * sc.y + bi.y, 0.f);
                if (MODE == 0) {
                    __half* C = (__half*)Cv;
                    *reinterpret_cast<__half2*>(C + (size_t)row * ldc + col) =
                        __floats2half2_rn(ox, oy);
                } else {
                    float* C = (float*)Cv;
                    float2 rr = *reinterpret_cast<const float2*>(
                        resid + (size_t)row * ldc + col);
                    float2 o = {ox + rr.x, oy + rr.y};
                    *reinterpret_cast<float2*>(C + (size_t)row * ldc + col) = o;
                }
            }
        }
    }
}

// ================ fp16 GEMM 256x128, 4-stage, continuous frag pipeline ========
// 8 warps in 4x2 grid, warp tile 64x64. K % 64 == 0 and K/64 >= 4 required.
// Cross-chunk fragment prefetch: wait_group 1 guarantees chunks <= c+1 resident
// after the barrier, so ks=3 prefetches (c+1, ks=0) and MMAs never start a
// chunk waiting on LDSM.
template<int MODE>
__global__ __launch_bounds__(256, 1) void gemm_mma_h2(
    const __half* __restrict__ A, const __half* __restrict__ Bm,
    const float* __restrict__ scale, const float* __restrict__ bias,
    const float* __restrict__ resid, void* __restrict__ Cv,
    int K, int lda, int ldb, int ldc)
{
    extern __shared__ __align__(128) char dynsmem[];
    const uint32_t sbase = smem_u32(dynsmem);
    const int tid  = threadIdx.x;
    const int lane = tid & 31;
    const int wid  = tid >> 5;
    const int wm   = wid >> 1;   // 0..3
    const int wn   = wid & 1;    // 0..1
    const int rowBase = blockIdx.y * 256;
    const int colBase = blockIdx.x * 128;

    const __half* Ablk = A  + (size_t)rowBase * lda;
    const __half* Bblk = Bm + (size_t)colBase * ldb;
    const int KT = K / 64;

    const int rA = wm * 64 + (lane & 15);
    const int rB = wn * 64 + (lane & 7);
    const int chA_half = (lane >> 4);
    const int tB_base  = (lane >> 4);
    const int chB_half = (lane >> 3) & 1;

    auto load_chunk = [&](int L) {
        const int s = L % NST2;
        const int k0 = L * 64;
        const uint32_t stage = sbase + s * STAGE2_BYTES;
        #pragma unroll
        for (int it = 0; it < 12; ++it) {
            int t = tid + it * 256;
            bool isB = t >= 2048;
            int tt = isB ? t - 2048 : t;
            int r = tt >> 3;
            int j = tt & 7;
            int gk = k0 + j * 8;
            const __half* src = (isB ? Bblk + (size_t)r * ldb
                                     : Ablk + (size_t)r * lda) + gk;
            uint32_t dst = stage + (isB ? 32768 : 0) + r * 128 + ((j ^ (r & 7)) << 4);
            asm volatile("cp.async.cg.shared.global [%0], [%1], 16;"
                         :: "r"(dst), "l"(src) : "memory");
        }
    };

    uint32_t af[2][4][4], bf[2][8][2];

    auto load_frags = [&](uint32_t ast, uint32_t bst, int ks, int pb) {
        #pragma unroll
        for (int mt = 0; mt < 4; ++mt) {
            int r = rA + mt * 16;
            int ch = ks * 2 + chA_half;
            uint32_t addr = ast + r * 128 + ((ch ^ (r & 7)) << 4);
            asm volatile("ldmatrix.sync.aligned.m8n8.x4.shared.b16 "
                         "{%0,%1,%2,%3}, [%4];"
                         : "=r"(af[pb][mt][0]), "=r"(af[pb][mt][1]),
                           "=r"(af[pb][mt][2]), "=r"(af[pb][mt][3])
                         : "r"(addr));
        }
        #pragma unroll
        for (int np = 0; np < 4; ++np) {
            int tile = np * 2 + tB_base;
            int r = rB + tile * 8;
            int ch = ks * 2 + chB_half;
            uint32_t addr = bst + r * 128 + ((ch ^ (r & 7)) << 4);
            asm volatile("ldmatrix.sync.aligned.m8n8.x4.shared.b16 "
                         "{%0,%1,%2,%3}, [%4];"
                         : "=r"(bf[pb][np * 2][0]), "=r"(bf[pb][np * 2][1]),
                           "=r"(bf[pb][np * 2 + 1][0]), "=r"(bf[pb][np * 2 + 1][1])
                         : "r"(addr));
        }
    };

    // ---- prologue: stages 0..2 in flight --------------------------------------
    #pragma unroll
    for (int p = 0; p < NST2 - 1; ++p) {
        load_chunk(p);                      // KT >= 4 guaranteed by callers
        asm volatile("cp.async.commit_group;" ::: "memory");
    }
    asm volatile("cp.async.wait_group 2;" ::: "memory");   // chunk 0 done
    __syncthreads();                                        // visible to all
    load_frags(sbase, sbase + 32768, 0, 0);                 // frags (0, ks=0)

    float acc[4][8][4];
    #pragma unroll
    for (int a = 0; a < 4; a++)
        #pragma unroll
        for (int b = 0; b < 8; b++)
            #pragma unroll
            for (int c = 0; c < 4; c++) acc[a][b][c] = 0.f;

    // ---- main loop -------------------------------------------------------------
    for (int c = 0; c < KT; ++c) {
        asm volatile("cp.async.wait_group 1;" ::: "memory");  // chunks <= c+1 done
        __syncthreads();                                       // ... and visible

        const uint32_t ast  = sbase + (c % NST2) * STAGE2_BYTES;
        const uint32_t bst  = ast + 32768;
        const uint32_t nast = sbase + ((c + 1) % NST2) * STAGE2_BYTES;
        const uint32_t nbst = nast + 32768;
        const int L = c + NST2 - 1;

        #pragma unroll
        for (int ks = 0; ks < 4; ++ks) {
            if (ks == 1) {                       // off the post-barrier path
                if (L < KT) load_chunk(L);
                asm volatile("cp.async.commit_group;" ::: "memory");
            }
            if (ks < 3)            load_frags(ast, bst, ks + 1, (ks + 1) & 1);
            else if (c + 1 < KT)   load_frags(nast, nbst, 0, 0);
            const int pb = ks & 1;
            #pragma unroll
            for (int mt = 0; mt < 4; ++mt)
                #pragma unroll
                for (int nt = 0; nt < 8; ++nt) {
                    asm volatile(
                        "mma.sync.aligned.m16n8k16.row.col.f32.f16.f16.f32 "
                        "{%0,%1,%2,%3}, {%4,%5,%6,%7}, {%8,%9}, {%0,%1,%2,%3};"
                        : "+f"(acc[mt][nt][0]), "+f"(acc[mt][nt][1]),
                          "+f"(acc[mt][nt][2]), "+f"(acc[mt][nt][3])
                        : "r"(af[pb][mt][0]), "r"(af[pb][mt][1]),
                          "r"(af[pb][mt][2]), "r"(af[pb][mt][3]),
                          "r"(bf[pb][nt][0]), "r"(bf[pb][nt][1]));
                }
        }
    }

    // ---- epilogue ----------------------------------------------------------------
    #pragma unroll
    for (int mt = 0; mt < 4; ++mt) {
        int r0 = rowBase + wm * 64 + mt * 16 + (lane >> 2);
        #pragma unroll
        for (int nt = 0; nt < 8; ++nt) {
            int col = colBase + wn * 64 + nt * 8 + (lane & 3) * 2;
            float2 sc = *reinterpret_cast<const float2*>(scale + col);
            float2 bi = *reinterpret_cast<const float2*>(bias + col);
            #pragma unroll
            for (int h = 0; h < 2; ++h) {
                int row = r0 + h * 8;
                float ox = fmaxf(acc[mt][nt][h * 2 + 0] * sc.x + bi.x, 0.f);
                float oy = fmaxf(acc[mt][nt][h * 2 + 1] * sc.y + bi.y, 0.f);
                if (MODE == 0) {
                    __half* C = (__half*)Cv;
                    *reinterpret_cast<__half2*>(C + (size_t)row * ldc + col) =
                        __floats2half2_rn(ox, oy);
                } else {
                    float* C = (float*)Cv;
                    float2 rr = *reinterpret_cast<const float2*>(
                        resid + (size_t)row * ldc + col);
                    float2 o = {ox + rr.x, oy + rr.y};
                    *reinterpret_cast<float2*>(C + (size_t)row * ldc + col) = o;
                }
            }
        }
    }
}

// ---------------------------------------------------------------------------
extern "C" void kernel_launch(void* const* d_in, const int* in_sizes, int n_in,
                              void* d_out, int out_size)
{
    const float* i_in   = (const float*)d_in[0];
    const float* s_in   = (const float*)d_in[1];
    const float* pi_in  = (const float*)d_in[2];
    const float* ps_in  = (const float*)d_in[3];
    const int*   mask_s = (const int*)  d_in[4];
    const float* vi = (const float*)d_in[5];
    const float* gi = (const float*)d_in[6];
    const float* bi = (const float*)d_in[7];
    const float* vs = (const float*)d_in[8];
    const float* gs = (const float*)d_in[9];
    const float* bs = (const float*)d_in[10];
    const float* vc = (const float*)d_in[11];
    const float* gc = (const float*)d_in[12];
    const float* bc = (const float*)d_in[13];
    float* out = (float*)d_out;

    float *att_p, *si_p, *ss_p, *sc_p;
    __half *sproj_p, *xcat_p, *i16_p, *s16_p, *vi16_p, *vs16_p, *vc16_p;
    cudaGetSymbolAddress((void**)&att_p,   g_att);
    cudaGetSymbolAddress((void**)&sproj_p, g_sproj);
    cudaGetSymbolAddress((void**)&xcat_p,  g_xcat);
    cudaGetSymbolAddress((void**)&si_p,    g_si);
    cudaGetSymbolAddress((void**)&ss_p,    g_ss);
    cudaGetSymbolAddress((void**)&sc_p,    g_sc);
    cudaGetSymbolAddress((void**)&i16_p,   g_i16);
    cudaGetSymbolAddress((void**)&s16_p,   g_s16);
    cudaGetSymbolAddress((void**)&vi16_p,  g_vi16);
    cudaGetSymbolAddress((void**)&vs16_p,  g_vs16);
    cudaGetSymbolAddress((void**)&vc16_p,  g_vc16);

    cudaFuncSetAttribute(gemm_mma_h<0>,  cudaFuncAttributeMaxDynamicSharedMemorySize, SMEM_DYN);
    cudaFuncSetAttribute(gemm_mma_h2<0>, cudaFuncAttributeMaxDynamicSharedMemorySize, SMEM_DYN2);
    cudaFuncSetAttribute(gemm_mma_h2<1>, cudaFuncAttributeMaxDynamicSharedMemorySize, SMEM_DYN2);

    // launch 0: fp16 conversion of all GEMM operands (fused)
    prep_convert_kernel<<<4096, 256>>>(i_in, i16_p, vi, vi16_p, vc, vc16_p,
                                       s_in, s16_p, vs, vs16_p);

    // launch 1: weight-norm scales + attention softmax (fused)
    prep2_kernel<<<RN_BLOCKS + ATT_BLOCKS, 256>>>(vi, gi, si_p, vs, gs, ss_p,
                                                  vc, gc, sc_p,
                                                  pi_in, ps_in, mask_s, att_p);

    // launch 2 (profiling slot landing zone): i_proj -> xcat[:, 0:1024]
    gemm_mma_h2<0><<<dim3(PROJ / 128, MI / 256), 256, SMEM_DYN2>>>(
        i16_p, vi16_p, si_p, bi, nullptr, xcat_p, OBJ, OBJ, OBJ, 2 * PROJ);

    // launch 3: s_proj = relu_wn(s @ Ws^T): [6400,300]x[1024,300]^T -> half
    gemm_mma_h<0><<<dim3(PROJ / 128, MS / 128), 256, SMEM_DYN>>>(
        s16_p, vs16_p, ss_p, bs, nullptr, sproj_p, SEM, SEMP, SEMP, PROJ);

    // launch 4: i_att -> xcat[:, 1024:2048]: batched [100,50]x[50,1024]
    attmm_kernel<<<dim3(B_, PROJ / 128), 256>>>(att_p, sproj_p, xcat_p);

    // launch 5: out = i + relu_wn(xcat @ Wc^T): [12800,4096]x[2048,4096]^T
    gemm_mma_h2<1><<<dim3(OBJ / 128, MI / 256), 256, SMEM_DYN2>>>(
        xcat_p, vc16_p, sc_p, bc, i_in, out, 2 * PROJ, 2 * PROJ, 2 * PROJ, OBJ);
}

// round 9
// speedup vs baseline: 9.8082x; 1.1528x over previous
#include <cuda_runtime.h>
#include <cuda_fp16.h>
#include <cstdint>
#include <cstddef>

// Problem constants
constexpr int B_   = 128;
constexpr int NI   = 100;
constexpr int NS   = 50;
constexpr int OBJ  = 2048;
constexpr int SEM  = 300;
constexpr int SEMP = 304;   // padded lda for fp16 s/vs (16B-aligned rows)
constexpr int PROJ = 1024;
constexpr int MI = B_ * NI;   // 12800
constexpr int MS = B_ * NS;   // 6400

// 128x128 GEMM pipeline (s_proj)
constexpr int NST = 3;
constexpr int STAGE_BYTES = 2 * 128 * 128;     // A 16KB + B 16KB
constexpr int SMEM_DYN = NST * STAGE_BYTES;    // 96 KB

// 256x128 GEMM pipeline (big GEMMs)
constexpr int NST2 = 4;
constexpr int STAGE2_BYTES = (256 + 128) * 128;   // A 32KB + B 16KB = 48KB
constexpr int SMEM_DYN2 = NST2 * STAGE2_BYTES;    // 192 KB

// ---------------- scratch (device globals; no runtime allocation) ------------
__device__ __align__(16) __half g_att16[(size_t)B_ * 128 * 64];     // padded att
__device__ __align__(16) __half g_sproj[(size_t)MS * PROJ];
__device__ __align__(16) __half g_sWT  [(size_t)OBJ * MS];          // [2048,6400]
__device__ __align__(16) __half g_T    [(size_t)MI * OBJ];          // att @ sW
__device__ __align__(16) __half g_iproj[(size_t)MI * PROJ];
__device__ __align__(16) __half g_i16  [(size_t)MI * OBJ];
__device__ __align__(16) __half g_s16  [(size_t)MS * SEMP];
__device__ __align__(16) __half g_vi16 [(size_t)PROJ * OBJ];
__device__ __align__(16) __half g_vs16 [(size_t)PROJ * SEMP];
__device__ __align__(16) __half g_vc16 [(size_t)OBJ * 2 * PROJ];
__device__ __align__(16) float  g_si[PROJ];
__device__ __align__(16) float  g_ss[PROJ];
__device__ __align__(16) float  g_sc[OBJ];

// ======================= helpers ==============================================
__device__ __forceinline__ uint32_t smem_u32(const void* p) {
    uint32_t a;
    asm("{ .reg .u64 t; cvta.to.shared.u64 t, %1; cvt.u32.u64 %0, t; }"
        : "=r"(a) : "l"(p));
    return a;
}

// ---------------- fused fp16 convert of the 5 GEMM operand buffers ------------
constexpr int CV_NI = MI * OBJ / 4;
constexpr int CV_NVI = PROJ * OBJ / 4;
constexpr int CV_NVC = OBJ * 2 * PROJ / 4;
constexpr int CV_DENSE = CV_NI + CV_NVI + CV_NVC;
constexpr int CV_NS = MS * SEM / 4;
constexpr int CV_NVS = PROJ * SEM / 4;
constexpr int CV_TOT = CV_DENSE + CV_NS + CV_NVS;

__global__ void prep_convert_kernel(const float* __restrict__ i_in, __half* __restrict__ i16,
                                    const float* __restrict__ vi,   __half* __restrict__ vi16,
                                    const float* __restrict__ vc,   __half* __restrict__ vc16,
                                    const float* __restrict__ s,    __half* __restrict__ s16,
                                    const float* __restrict__ vs,   __half* __restrict__ vs16)
{
    for (int t = blockIdx.x * blockDim.x + threadIdx.x; t < CV_TOT;
         t += gridDim.x * blockDim.x) {
        const float* src; __half* dst; int j = t, dj;
        if (j < CV_NI)                      { src = i_in; dst = i16;  dj = j; }
        else if ((j -= CV_NI) < CV_NVI)     { src = vi;   dst = vi16; dj = j; }
        else if ((j -= CV_NVI) < CV_NVC)    { src = vc;   dst = vc16; dj = j; }
        else if ((j -= CV_NVC) < CV_NS) {
            src = s;  dst = s16;
            int row = j / 75, c = j % 75;
            float4 v = reinterpret_cast<const float4*>(src)[j];
            __half2* d = reinterpret_cast<__half2*>(dst + (size_t)row * SEMP + c * 4);
            d[0] = __floats2half2_rn(v.x, v.y);
            d[1] = __floats2half2_rn(v.z, v.w);
            continue;
        } else {
            j -= CV_NS;
            src = vs; dst = vs16;
            int row = j / 75, c = j % 75;
            float4 v = reinterpret_cast<const float4*>(src)[j];
            __half2* d = reinterpret_cast<__half2*>(dst + (size_t)row * SEMP + c * 4);
            d[0] = __floats2half2_rn(v.x, v.y);
            d[1] = __floats2half2_rn(v.z, v.w);
            continue;
        }
        float4 v = reinterpret_cast<const float4*>(src)[dj];
        __half2* d = reinterpret_cast<__half2*>(dst + (size_t)dj * 4);
        d[0] = __floats2half2_rn(v.x, v.y);
        d[1] = __floats2half2_rn(v.z, v.w);
    }
}

// ------- fused row-norm scales + attention softmax (fp16, padded 128x64) -------
constexpr int RN_BLOCKS = 2 * PROJ + OBJ;
constexpr int ATT_BLOCKS = B_ * 128 / 256;   // 64

__global__ void prep2_kernel(const float* __restrict__ vi, const float* __restrict__ gi,
                             float* __restrict__ si,
                             const float* __restrict__ vs, const float* __restrict__ gs,
                             float* __restrict__ ss,
                             const float* __restrict__ vc, const float* __restrict__ gc,
                             float* __restrict__ sc,
                             const float* __restrict__ pi, const float* __restrict__ ps,
                             const int* __restrict__ mask_s, __half* __restrict__ att16)
{
    int blk = blockIdx.x;
    if (blk >= RN_BLOCKS) {
        // ---- attention softmax into [B][128][64] fp16, zero-padded ----
        int idx = (blk - RN_BLOCKS) * blockDim.x + threadIdx.x;   // 0..16383
        int b = idx >> 7;
        int m = idx & 127;
        __half2* orow = reinterpret_cast<__half2*>(att16 + (size_t)idx * 64);
        if (m >= NI) {
            #pragma unroll
            for (int j = 0; j < 32; j++) orow[j] = __halves2half2(__half(0.f), __half(0.f));
            return;
        }
        int rix = b * NI + m;
        float px = pi[rix * 2 + 0];
        float py = pi[rix * 2 + 1];
        int mm = mask_s[b];
        const float* psb = ps + (size_t)b * NS * 2;

        float d[NS];
        float mx = -1e30f;
        #pragma unroll
        for (int j = 0; j < NS; j++) {
            float dx = px - psb[2 * j + 0];
            float dy = py - psb[2 * j + 1];
            d[j] = sqrtf(dx * dx + dy * dy);
            if (j < mm) mx = fmaxf(mx, d[j]);
        }
        float sum = 0.f;
        #pragma unroll
        for (int j = 0; j < NS; j++) {
            float e = (j < mm) ? __expf(d[j] - mx) : 0.f;
            d[j] = e;
            sum += e;
        }
        float inv = 1.f / sum;
        #pragma unroll
        for (int j = 0; j < 32; j++) {
            float lo = (2 * j     < NS) ? d[2 * j]     * inv : 0.f;
            float hi = (2 * j + 1 < NS) ? d[2 * j + 1] * inv : 0.f;
            orow[j] = __floats2half2_rn(lo, hi);
        }
        return;
    }
    // ---- rownorm ----
    const float *v, *g; float* out; int K, r;
    if (blk < PROJ)            { v = vi; g = gi; out = si; K = OBJ;      r = blk; }
    else if (blk < 2 * PROJ)   { v = vs; g = gs; out = ss; K = SEM;      r = blk - PROJ; }
    else                       { v = vc; g = gc; out = sc; K = 2 * PROJ; r = blk - 2 * PROJ; }

    float s = 0.f;
    for (int k = threadIdx.x; k < K; k += blockDim.x) {
        float x = v[(size_t)r * K + k];
        s += x * x;
    }
    __shared__ float red[256];
    red[threadIdx.x] = s;
    __syncthreads();
    #pragma unroll
    for (int o = 128; o > 0; o >>= 1) {
        if (threadIdx.x < o) red[threadIdx.x] += red[threadIdx.x + o];
        __syncthreads();
    }
    if (threadIdx.x == 0) out[r] = g[r] * rsqrtf(red[0]);
}

// ----------- tensor-core batched attmm: T[b*100+m, n] = att @ sW --------------
// per CTA: batch b, n-tile of 128.  A = att16 [128m x 64k], B = sWT rows.
__global__ __launch_bounds__(256) void attmm_tc_kernel(
    const __half* __restrict__ att16,   // [B][128][64]
    const __half* __restrict__ sWT,     // [2048][6400]  (n-major, token cols)
    __half* __restrict__ T)             // [12800][2048]
{
    __shared__ __align__(16) char smem[32 * 1024];
    const uint32_t As = smem_u32(smem);
    const uint32_t Bs = As + 16384;
    const int b    = blockIdx.y;
    const int ncol = blockIdx.x * 128;
    const int tid  = threadIdx.x;
    const int lane = tid & 31;
    const int wid  = tid >> 5;
    const int wm   = wid >> 1;   // 0..3 -> 32 m-rows each
    const int wn   = wid & 1;    // 0..1 -> 64 n-cols each

    // A tile: att16[b] 128 rows x 128B, cp.async + XOR swizzle
    #pragma unroll
    for (int it = 0; it < 4; ++it) {
        int e = tid + it * 256;            // 0..1023
        int r = e >> 3, j = e & 7;
        const __half* src = att16 + ((size_t)(b * 128 + r)) * 64 + j * 8;
        uint32_t dst = As + r * 128 + ((j ^ (r & 7)) << 4);
        asm volatile("cp.async.cg.shared.global [%0], [%1], 16;"
                     :: "r"(dst), "l"(src) : "memory");
    }
    asm volatile("cp.async.commit_group;" ::: "memory");

    // B tile: 128 n-rows x 64 k(tokens), rows of sWT; coalesced LDG, pad k>=50
    {
        const uint32_t* swt32 = reinterpret_cast<const uint32_t*>(sWT);
        #pragma unroll
        for (int i = 0; i < 16; ++i) {
            int n = wid * 16 + i;
            int j = lane;                              // word index 0..31
            uint32_t val = 0;
            if (j < 25)
                val = swt32[(size_t)(ncol + n) * 3200 + b * 25 + j];
            uint32_t dst = Bs + n * 128 + ((((j >> 2) ^ (n & 7)) << 4) | ((j & 3) * 4));
            asm volatile("st.shared.b32 [%0], %1;" :: "r"(dst), "r"(val) : "memory");
        }
    }
    asm volatile("cp.async.wait_group 0;" ::: "memory");
    __syncthreads();

    float acc[2][8][4];
    #pragma unroll
    for (int a = 0; a < 2; a++)
        #pragma unroll
        for (int n = 0; n < 8; n++)
            #pragma unroll
            for (int c = 0; c < 4; c++) acc[a][n][c] = 0.f;

    const int rA = wm * 32 + (lane & 15);
    const int rB = wn * 64 + (lane & 7);
    #pragma unroll
    for (int ks = 0; ks < 4; ++ks) {
        uint32_t af[2][4], bf[8][2];
        #pragma unroll
        for (int mt = 0; mt < 2; ++mt) {
            int r = rA + mt * 16;
            int ch = ks * 2 + (lane >> 4);
            uint32_t addr = As + r * 128 + ((ch ^ (r & 7)) << 4);
            asm volatile("ldmatrix.sync.aligned.m8n8.x4.shared.b16 "
                         "{%0,%1,%2,%3}, [%4];"
                         : "=r"(af[mt][0]), "=r"(af[mt][1]),
                           "=r"(af[mt][2]), "=r"(af[mt][3])
                         : "r"(addr));
        }
        #pragma unroll
        for (int np = 0; np < 4; ++np) {
            int tile = np * 2 + (lane >> 4);
            int r = rB + tile * 8;
            int ch = ks * 2 + ((lane >> 3) & 1);
            uint32_t addr = Bs + r * 128 + ((ch ^ (r & 7)) << 4);
            asm volatile("ldmatrix.sync.aligned.m8n8.x4.shared.b16 "
                         "{%0,%1,%2,%3}, [%4];"
                         : "=r"(bf[np * 2][0]), "=r"(bf[np * 2][1]),
                           "=r"(bf[np * 2 + 1][0]), "=r"(bf[np * 2 + 1][1])
                         : "r"(addr));
        }
        #pragma unroll
        for (int mt = 0; mt < 2; ++mt)
            #pragma unroll
            for (int nt = 0; nt < 8; ++nt) {
                asm volatile(
                    "mma.sync.aligned.m16n8k16.row.col.f32.f16.f16.f32 "
                    "{%0,%1,%2,%3}, {%4,%5,%6,%7}, {%8,%9}, {%0,%1,%2,%3};"
                    : "+f"(acc[mt][nt][0]), "+f"(acc[mt][nt][1]),
                      "+f"(acc[mt][nt][2]), "+f"(acc[mt][nt][3])
                    : "r"(af[mt][0]), "r"(af[mt][1]),
                      "r"(af[mt][2]), "r"(af[mt][3]),
                      "r"(bf[nt][0]), "r"(bf[nt][1]));
            }
    }

    // epilogue: rows m < 100 only
    #pragma unroll
    for (int mt = 0; mt < 2; ++mt) {
        int m0 = wm * 32 + mt * 16 + (lane >> 2);
        #pragma unroll
        for (int h = 0; h < 2; ++h) {
            int m = m0 + h * 8;
            if (m >= NI) continue;
            size_t rowoff = (size_t)(b * NI + m) * OBJ;
            #pragma unroll
            for (int nt = 0; nt < 8; ++nt) {
                int col = ncol + wn * 64 + nt * 8 + (lane & 3) * 2;
                *reinterpret_cast<__half2*>(T + rowoff + col) =
                    __floats2half2_rn(acc[mt][nt][h * 2 + 0], acc[mt][nt][h * 2 + 1]);
            }
        }
    }
}

// ================ fp16 GEMM 128x128 (s_proj; handles K tails) =================
__global__ __launch_bounds__(256, 2) void gemm_mma_h(
    const __half* __restrict__ A, const __half* __restrict__ Bm,
    const float* __restrict__ scale, const float* __restrict__ bias,
    __half* __restrict__ C,
    int K, int lda, int ldb, int ldc)
{
    extern __shared__ __align__(128) char dynsmem[];
    const uint32_t sbase = smem_u32(dynsmem);
    const int tid  = threadIdx.x;
    const int lane = tid & 31;
    const int wid  = tid >> 5;
    const int wm   = wid >> 2;
    const int wn   = wid & 3;
    const int rowBase = blockIdx.y * 128;
    const int colBase = blockIdx.x * 128;

    const __half* Ablk = A  + (size_t)rowBase * lda;
    const __half* Bblk = Bm + (size_t)colBase * ldb;
    const int KT = (K + 63) / 64;

    auto load_chunk = [&](int L) {
        const int s = L % NST;
        const int k0 = L * 64;
        const uint32_t stage = sbase + s * STAGE_BYTES;
        const bool tail = (k0 + 64 > K);
        #pragma unroll
        for (int it = 0; it < 8; ++it) {
            int t = tid + it * 256;
            int which = t >> 10;
            int r = (t >> 3) & 127;
            int j = t & 7;
            int gk = k0 + j * 8;
            const __half* src = (which ? Bblk + (size_t)r * ldb
                                       : Ablk + (size_t)r * lda) + gk;
            uint32_t dst = stage + which * 16384 + r * 128 + ((j ^ (r & 7)) << 4);
            if (!tail) {
                asm volatile("cp.async.cg.shared.global [%0], [%1], 16;"
                             :: "r"(dst), "l"(src) : "memory");
            } else {
                uint32_t w[4];
                #pragma unroll
                for (int u = 0; u < 4; ++u) {
                    __half lo = (gk + 2 * u     < K) ? src[2 * u]     : __half(0.f);
                    __half hi = (gk + 2 * u + 1 < K) ? src[2 * u + 1] : __half(0.f);
                    __half2 h2 = __halves2half2(lo, hi);
                    w[u] = *reinterpret_cast<uint32_t*>(&h2);
                }
                asm volatile("st.shared.v4.b32 [%0], {%1,%2,%3,%4};"
                             :: "r"(dst), "r"(w[0]), "r"(w[1]), "r"(w[2]), "r"(w[3])
                             : "memory");
            }
        }
    };

    #pragma unroll
    for (int p = 0; p < NST - 1; ++p) {
        if (p < KT) load_chunk(p);
        asm volatile("cp.async.commit_group;" ::: "memory");
    }

    float acc[4][4][4];
    #pragma unroll
    for (int a = 0; a < 4; a++)
        #pragma unroll
        for (int b = 0; b < 4; b++)
            #pragma unroll
            for (int c = 0; c < 4; c++) acc[a][b][c] = 0.f;

    for (int c = 0; c < KT; ++c) {
        asm volatile("cp.async.wait_group 1;" ::: "memory");
        __syncthreads();

        const int L = c + NST - 1;
        if (L < KT) load_chunk(L);
        asm volatile("cp.async.commit_group;" ::: "memory");

        const uint32_t ast = sbase + (c % NST) * STAGE_BYTES;
        const uint32_t bst = ast + 16384;

        #pragma unroll
        for (int ks = 0; ks < 4; ++ks) {
            uint32_t af[4][4], bf[4][2];
            #pragma unroll
            for (int mt = 0; mt < 4; ++mt) {
                int r = wm * 64 + mt * 16 + (lane & 15);
                int ch = ks * 2 + (lane >> 4);
                uint32_t addr = ast + r * 128 + ((ch ^ (r & 7)) << 4);
                asm volatile("ldmatrix.sync.aligned.m8n8.x4.shared.b16 "
                             "{%0,%1,%2,%3}, [%4];"
                             : "=r"(af[mt][0]), "=r"(af[mt][1]),
                               "=r"(af[mt][2]), "=r"(af[mt][3])
                             : "r"(addr));
            }
            #pragma unroll
            for (int np = 0; np < 2; ++np) {
                int tile = np * 2 + (lane >> 4);
                int half_k = (lane >> 3) & 1;
                int r = wn * 32 + tile * 8 + (lane & 7);
                int ch = ks * 2 + half_k;
                uint32_t addr = bst + r * 128 + ((ch ^ (r & 7)) << 4);
                asm volatile("ldmatrix.sync.aligned.m8n8.x4.shared.b16 "
                             "{%0,%1,%2,%3}, [%4];"
                             : "=r"(bf[np * 2][0]), "=r"(bf[np * 2][1]),
                               "=r"(bf[np * 2 + 1][0]), "=r"(bf[np * 2 + 1][1])
                             : "r"(addr));
            }
            #pragma unroll
            for (int mt = 0; mt < 4; ++mt)
                #pragma unroll
                for (int nt = 0; nt < 4; ++nt) {
                    asm volatile(
                        "mma.sync.aligned.m16n8k16.row.col.f32.f16.f16.f32 "
                        "{%0,%1,%2,%3}, {%4,%5,%6,%7}, {%8,%9}, {%0,%1,%2,%3};"
                        : "+f"(acc[mt][nt][0]), "+f"(acc[mt][nt][1]),
                          "+f"(acc[mt][nt][2]), "+f"(acc[mt][nt][3])
                        : "r"(af[mt][0]), "r"(af[mt][1]),
                          "r"(af[mt][2]), "r"(af[mt][3]),
                          "r"(bf[nt][0]), "r"(bf[nt][1]));
                }
        }
    }

    #pragma unroll
    for (int mt = 0; mt < 4; ++mt) {
        int r0 = rowBase + wm * 64 + mt * 16 + (lane >> 2);
        #pragma unroll
        for (int nt = 0; nt < 4; ++nt) {
            int col = colBase + wn * 32 + nt * 8 + (lane & 3) * 2;
            float2 sc = *reinterpret_cast<const float2*>(scale + col);
            float2 bi = *reinterpret_cast<const float2*>(bias + col);
            #pragma unroll
            for (int h = 0; h < 2; ++h) {
                int row = r0 + h * 8;
                float ox = fmaxf(acc[mt][nt][h * 2 + 0] * sc.x + bi.x, 0.f);
                float oy = fmaxf(acc[mt][nt][h * 2 + 1] * sc.y + bi.y, 0.f);
                *reinterpret_cast<__half2*>(C + (size_t)row * ldc + col) =
                    __floats2half2_rn(ox, oy);
            }
        }
    }
}

// ====== fp16 GEMM 256x128, 4-stage, continuous frag pipeline ==================
// MODE 0: C(half)  = relu(acc*scale+bias)
// MODE 2: C(half)  = acc (raw)
// MODE 3: C(float) = resid + relu(scale*(acc + T) + bias)
template<int MODE>
__global__ __launch_bounds__(256, 1) void gemm_mma_h2(
    const __half* __restrict__ A, const __half* __restrict__ Bm,
    const float* __restrict__ scale, const float* __restrict__ bias,
    const float* __restrict__ resid, const __half* __restrict__ Tadd,
    void* __restrict__ Cv,
    int K, int lda, int ldb, int ldc)
{
    extern __shared__ __align__(128) char dynsmem[];
    const uint32_t sbase = smem_u32(dynsmem);
    const int tid  = threadIdx.x;
    const int lane = tid & 31;
    const int wid  = tid >> 5;
    const int wm   = wid >> 1;
    const int wn   = wid & 1;
    const int rowBase = blockIdx.y * 256;
    const int colBase = blockIdx.x * 128;

    const __half* Ablk = A  + (size_t)rowBase * lda;
    const __half* Bblk = Bm + (size_t)colBase * ldb;
    const int KT = K / 64;

    const int rA = wm * 64 + (lane & 15);
    const int rB = wn * 64 + (lane & 7);
    const int chA_half = (lane >> 4);
    const int tB_base  = (lane >> 4);
    const int chB_half = (lane >> 3) & 1;

    auto load_chunk = [&](int L) {
        const int s = L % NST2;
        const int k0 = L * 64;
        const uint32_t stage = sbase + s * STAGE2_BYTES;
        #pragma unroll
        for (int it = 0; it < 12; ++it) {
            int t = tid + it * 256;
            bool isB = t >= 2048;
            int tt = isB ? t - 2048 : t;
            int r = tt >> 3;
            int j = tt & 7;
            int gk = k0 + j * 8;
            const __half* src = (isB ? Bblk + (size_t)r * ldb
                                     : Ablk + (size_t)r * lda) + gk;
            uint32_t dst = stage + (isB ? 32768 : 0) + r * 128 + ((j ^ (r & 7)) << 4);
            asm volatile("cp.async.cg.shared.global [%0], [%1], 16;"
                         :: "r"(dst), "l"(src) : "memory");
        }
    };

    uint32_t af[2][4][4], bf[2][8][2];

    auto load_frags = [&](uint32_t ast, uint32_t bst, int ks, int pb) {
        #pragma unroll
        for (int mt = 0; mt < 4; ++mt) {
            int r = rA + mt * 16;
            int ch = ks * 2 + chA_half;
            uint32_t addr = ast + r * 128 + ((ch ^ (r & 7)) << 4);
            asm volatile("ldmatrix.sync.aligned.m8n8.x4.shared.b16 "
                         "{%0,%1,%2,%3}, [%4];"
                         : "=r"(af[pb][mt][0]), "=r"(af[pb][mt][1]),
                           "=r"(af[pb][mt][2]), "=r"(af[pb][mt][3])
                         : "r"(addr));
        }
        #pragma unroll
        for (int np = 0; np < 4; ++np) {
            int tile = np * 2 + tB_base;
            int r = rB + tile * 8;
            int ch = ks * 2 + chB_half;
            uint32_t addr = bst + r * 128 + ((ch ^ (r & 7)) << 4);
            asm volatile("ldmatrix.sync.aligned.m8n8.x4.shared.b16 "
                         "{%0,%1,%2,%3}, [%4];"
                         : "=r"(bf[pb][np * 2][0]), "=r"(bf[pb][np * 2][1]),
                           "=r"(bf[pb][np * 2 + 1][0]), "=r"(bf[pb][np * 2 + 1][1])
                         : "r"(addr));
        }
    };

    #pragma unroll
    for (int p = 0; p < NST2 - 1; ++p) {
        load_chunk(p);
        asm volatile("cp.async.commit_group;" ::: "memory");
    }
    asm volatile("cp.async.wait_group 2;" ::: "memory");
    __syncthreads();
    load_frags(sbase, sbase + 32768, 0, 0);

    float acc[4][8][4];
    #pragma unroll
    for (int a = 0; a < 4; a++)
        #pragma unroll
        for (int b = 0; b < 8; b++)
            #pragma unroll
            for (int c = 0; c < 4; c++) acc[a][b][c] = 0.f;

    for (int c = 0; c < KT; ++c) {
        asm volatile("cp.async.wait_group 1;" ::: "memory");
        __syncthreads();

        const uint32_t ast  = sbase + (c % NST2) * STAGE2_BYTES;
        const uint32_t bst  = ast + 32768;
        const uint32_t nast = sbase + ((c + 1) % NST2) * STAGE2_BYTES;
        const uint32_t nbst = nast + 32768;
        const int L = c + NST2 - 1;

        #pragma unroll
        for (int ks = 0; ks < 4; ++ks) {
            if (ks == 1) {
                if (L < KT) load_chunk(L);
                asm volatile("cp.async.commit_group;" ::: "memory");
            }
            if (ks < 3)            load_frags(ast, bst, ks + 1, (ks + 1) & 1);
            else if (c + 1 < KT)   load_frags(nast, nbst, 0, 0);
            const int pb = ks & 1;
            #pragma unroll
            for (int mt = 0; mt < 4; ++mt)
                #pragma unroll
                for (int nt = 0; nt < 8; ++nt) {
                    asm volatile(
                        "mma.sync.aligned.m16n8k16.row.col.f32.f16.f16.f32 "
                        "{%0,%1,%2,%3}, {%4,%5,%6,%7}, {%8,%9}, {%0,%1,%2,%3};"
                        : "+f"(acc[mt][nt][0]), "+f"(acc[mt][nt][1]),
                          "+f"(acc[mt][nt][2]), "+f"(acc[mt][nt][3])
                        : "r"(af[pb][mt][0]), "r"(af[pb][mt][1]),
                          "r"(af[pb][mt][2]), "r"(af[pb][mt][3]),
                          "r"(bf[pb][nt][0]), "r"(bf[pb][nt][1]));
                }
        }
    }

    #pragma unroll
    for (int mt = 0; mt < 4; ++mt) {
        int r0 = rowBase + wm * 64 + mt * 16 + (lane >> 2);
        #pragma unroll
        for (int nt = 0; nt < 8; ++nt) {
            int col = colBase + wn * 64 + nt * 8 + (lane & 3) * 2;
            float2 sc, bi;
            if (MODE != 2) {
                sc = *reinterpret_cast<const float2*>(scale + col);
                bi = *reinterpret_cast<const float2*>(bias + col);
            }
            #pragma unroll
            for (int h = 0; h < 2; ++h) {
                int row = r0 + h * 8;
                float ax = acc[mt][nt][h * 2 + 0];
                float ay = acc[mt][nt][h * 2 + 1];
                if (MODE == 2) {
                    __half* C = (__half*)Cv;
                    *reinterpret_cast<__half2*>(C + (size_t)row * ldc + col) =
                        __floats2half2_rn(ax, ay);
                } else if (MODE == 0) {
                    float ox = fmaxf(ax * sc.x + bi.x, 0.f);
                    float oy = fmaxf(ay * sc.y + bi.y, 0.f);
                    __half* C = (__half*)Cv;
                    *reinterpret_cast<__half2*>(C + (size_t)row * ldc + col) =
                        __floats2half2_rn(ox, oy);
                } else {  // MODE 3
                    __half2 th = *reinterpret_cast<const __half2*>(
                        Tadd + (size_t)row * ldc + col);
                    float2 tf = __half22float2(th);
                    float ox = fmaxf((ax + tf.x) * sc.x + bi.x, 0.f);
                    float oy = fmaxf((ay + tf.y) * sc.y + bi.y, 0.f);
                    float2 rr = *reinterpret_cast<const float2*>(
                        resid + (size_t)row * ldc + col);
                    float2 o = {ox + rr.x, oy + rr.y};
                    float* C = (float*)Cv;
                    *reinterpret_cast<float2*>(C + (size_t)row * ldc + col) = o;
                }
            }
        }
    }
}

// ---------------------------------------------------------------------------
extern "C" void kernel_launch(void* const* d_in, const int* in_sizes, int n_in,
                              void* d_out, int out_size)
{
    const float* i_in   = (const float*)d_in[0];
    const float* s_in   = (const float*)d_in[1];
    const float* pi_in  = (const float*)d_in[2];
    const float* ps_in  = (const float*)d_in[3];
    const int*   mask_s = (const int*)  d_in[4];
    const float* vi = (const float*)d_in[5];
    const float* gi = (const float*)d_in[6];
    const float* bi = (const float*)d_in[7];
    const float* vs = (const float*)d_in[8];
    const float* gs = (const float*)d_in[9];
    const float* bs = (const float*)d_in[10];
    const float* vc = (const float*)d_in[11];
    const float* gc = (const float*)d_in[12];
    const float* bc = (const float*)d_in[13];
    float* out = (float*)d_out;

    float *si_p, *ss_p, *sc_p;
    __half *att16_p, *sproj_p, *sWT_p, *T_p, *iproj_p;
    __half *i16_p, *s16_p, *vi16_p, *vs16_p, *vc16_p;
    cudaGetSymbolAddress((void**)&att16_p, g_att16);
    cudaGetSymbolAddress((void**)&sproj_p, g_sproj);
    cudaGetSymbolAddress((void**)&sWT_p,   g_sWT);
    cudaGetSymbolAddress((void**)&T_p,     g_T);
    cudaGetSymbolAddress((void**)&iproj_p, g_iproj);
    cudaGetSymbolAddress((void**)&si_p,    g_si);
    cudaGetSymbolAddress((void**)&ss_p,    g_ss);
    cudaGetSymbolAddress((void**)&sc_p,    g_sc);
    cudaGetSymbolAddress((void**)&i16_p,   g_i16);
    cudaGetSymbolAddress((void**)&s16_p,   g_s16);
    cudaGetSymbolAddress((void**)&vi16_p,  g_vi16);
    cudaGetSymbolAddress((void**)&vs16_p,  g_vs16);
    cudaGetSymbolAddress((void**)&vc16_p,  g_vc16);

    cudaFuncSetAttribute(gemm_mma_h,     cudaFuncAttributeMaxDynamicSharedMemorySize, SMEM_DYN);
    cudaFuncSetAttribute(gemm_mma_h2<0>, cudaFuncAttributeMaxDynamicSharedMemorySize, SMEM_DYN2);
    cudaFuncSetAttribute(gemm_mma_h2<2>, cudaFuncAttributeMaxDynamicSharedMemorySize, SMEM_DYN2);
    cudaFuncSetAttribute(gemm_mma_h2<3>, cudaFuncAttributeMaxDynamicSharedMemorySize, SMEM_DYN2);

    // launch 0: fp16 conversion of all GEMM operands (fused)
    prep_convert_kernel<<<4096, 256>>>(i_in, i16_p, vi, vi16_p, vc, vc16_p,
                                       s_in, s16_p, vs, vs16_p);

    // launch 1: weight-norm scales + fp16 attention (padded 128x64/batch)
    prep2_kernel<<<RN_BLOCKS + ATT_BLOCKS, 256>>>(vi, gi, si_p, vs, gs, ss_p,
                                                  vc, gc, sc_p,
                                                  pi_in, ps_in, mask_s, att16_p);

    // launch 2: s_proj = relu_wn(s @ Ws^T): [6400,300]x[1024,300]^T -> half
    gemm_mma_h<<<dim3(PROJ / 128, MS / 128), 256, SMEM_DYN>>>(
        s16_p, vs16_p, ss_p, bs, sproj_p, SEM, SEMP, SEMP, PROJ);

    // launch 3: sWT = Wc2 @ s_proj^T: M=2048, N=6400, K=1024 -> [2048,6400] half
    gemm_mma_h2<2><<<dim3(MS / 128, OBJ / 256), 256, SMEM_DYN2>>>(
        vc16_p + PROJ, sproj_p, nullptr, nullptr, nullptr, nullptr, sWT_p,
        PROJ, 2 * PROJ, PROJ, MS);

    // launch 4: i_proj = relu_wn(i @ Wi^T): [12800,2048]x[1024,2048]^T -> half
    gemm_mma_h2<0><<<dim3(PROJ / 128, MI / 256), 256, SMEM_DYN2>>>(
        i16_p, vi16_p, si_p, bi, nullptr, nullptr, iproj_p,
        OBJ, OBJ, OBJ, PROJ);

    // launch 5: T = att @ sW per batch (tensor-core batched small GEMM)
    attmm_tc_kernel<<<dim3(OBJ / 128, B_), 256>>>(att16_p, sWT_p, T_p);

    // launch 6: out = i + relu(sc*(i_proj@Wc1^T + T) + bc): K=1024
    gemm_mma_h2<3><<<dim3(OBJ / 128, MI / 256), 256, SMEM_DYN2>>>(
        iproj_p, vc16_p, sc_p, bc, i_in, T_p, out,
        PROJ, PROJ, 2 * PROJ, OBJ);
}